// round 1
// baseline (speedup 1.0000x reference)
#include <cuda_runtime.h>
#include <cuda_bf16.h>

#define EPSF 1e-8f
#define LAMBDAF 1e-3f
#define LN2PI_HALF_F 0.91893853320467274178f

// ---------------- network dims ----------------
#define NB 32           // batch
#define H0 64           // input
#define H1 30           // after conv1 (k5 s2 valid)
#define C1 64
#define B1 8            // primary capsule types
#define PS 16
#define H2 15           // after dw1 (k7 s2 pad3)
#define CC1_IN 8
#define CC1_OUT 16
#define H3 8            // after dw2 (k5 s2 pad2)
#define CC2_IN 16
#define CC2_OUT 16
#define CLS_D 16
#define CLS_E 10
#define CLS_BIN (H3*H3*CLS_D)   // 1024

// ---------------- scratch ----------------
__device__ float g_y    [NB*H1*H1*C1];          // conv1 out
__device__ float g_pose1[NB*H1*H1*B1*PS];
__device__ float g_a1   [NB*H1*H1*B1];
__device__ float g_pose2[NB*H2*H2*B1*PS];       // dw1 out
__device__ float g_a2   [NB*H2*H2*B1];
__device__ float g_pose3[NB*H2*H2*CC1_OUT*PS];  // cc1 out
__device__ float g_a3   [NB*H2*H2*CC1_OUT];
__device__ float g_pose4[NB*H3*H3*CC1_OUT*PS];  // dw2 out
__device__ float g_a4   [NB*H3*H3*CC1_OUT];
__device__ float g_pose5[NB*H3*H3*CC2_OUT*PS];  // cc2 out
__device__ float g_a5   [NB*H3*H3*CC2_OUT];
__device__ float g_votes[NB*CLS_BIN*CLS_E*PS];  // class votes

__device__ __forceinline__ float sigmoidf_(float x){ return 1.0f/(1.0f+expf(-x)); }
__device__ __forceinline__ float wred(float v){
    #pragma unroll
    for (int o=16;o;o>>=1) v += __shfl_xor_sync(0xffffffffu, v, o);
    return v;
}

// ---------------- 1: conv stem + relu ----------------
__global__ void __launch_bounds__(256) conv1_kernel(
    const float* __restrict__ x, const float* __restrict__ w,
    const float* __restrict__ bias)
{
    int idx = blockIdx.x*256 + threadIdx.x;
    const int total = NB*H1*H1*C1;
    if (idx >= total) return;
    int co = idx & 63;
    int t  = idx >> 6;
    int ox = t % H1; t /= H1;
    int oy = t % H1; int b = t / H1;
    float s = bias[co];
    const float* xb = x + (size_t)b*H0*H0;
    #pragma unroll
    for (int kh=0; kh<5; kh++){
        const float* xr = xb + (oy*2+kh)*H0 + ox*2;
        #pragma unroll
        for (int kw=0; kw<5; kw++)
            s += xr[kw] * w[(kh*5+kw)*64 + co];
    }
    g_y[idx] = fmaxf(s, 0.0f);
}

// ---------------- 2: primary caps (pose + activation) ----------------
__global__ void __launch_bounds__(256) prim_kernel(
    const float* __restrict__ Wp, const float* __restrict__ bp,
    const float* __restrict__ Wa, const float* __restrict__ ba)
{
    int idx = blockIdx.x*256 + threadIdx.x;
    const int total = NB*H1*H1*136;
    if (idx >= total) return;
    int d = idx % 136;
    int pos = idx / 136;
    const float* yy = g_y + (size_t)pos*C1;
    if (d < 128){
        float s = bp[d];
        #pragma unroll 8
        for (int c=0;c<C1;c++) s += yy[c]*Wp[c*128+d];
        g_pose1[(size_t)pos*128 + d] = s;
    } else {
        int da = d - 128;
        float s = ba[da];
        #pragma unroll 8
        for (int c=0;c<C1;c++) s += yy[c]*Wa[c*8+da];
        g_a1[(size_t)pos*8 + da] = sigmoidf_(s);
    }
}

// ---------------- depthwise caps (Cout=1 => single M-step) ----------------
template<int K, int PAD, int HIN, int HOUT, int BC>
__global__ void __launch_bounds__(128) dw_caps_kernel(
    const float* __restrict__ pose_in,  // (NB,HIN,HIN,BC*16)
    const float* __restrict__ a_in_g,   // (NB,HIN,HIN,BC)
    const float* __restrict__ W,        // (K*K, BC, 4, 4)
    const float* __restrict__ bu, const float* __restrict__ ba,
    float* __restrict__ pose_out,       // (NB,HOUT,HOUT,BC*16)
    float* __restrict__ a_out_g)        // (NB,HOUT,HOUT,BC)
{
    int idx = blockIdx.x*128 + threadIdx.x;
    const int total = NB*HOUT*HOUT*BC;
    if (idx >= total) return;
    int c  = idx % BC;
    int t  = idx / BC;
    int ox = t % HOUT; t /= HOUT;
    int oy = t % HOUT; int b = t / HOUT;

    // pass 0: r_sum = sum of activations over valid patch
    float r_sum = 0.0f;
    for (int ki=0; ki<K; ki++){
        int iy = oy*2 + ki - PAD;
        if (iy < 0 || iy >= HIN) continue;
        for (int kj=0; kj<K; kj++){
            int ix = ox*2 + kj - PAD;
            if (ix < 0 || ix >= HIN) continue;
            r_sum += a_in_g[((b*HIN+iy)*HIN+ix)*BC + c];
        }
    }
    float inv = 1.0f/(r_sum + EPSF);

    // pass 1: weighted mean of votes
    float mu[16];
    #pragma unroll
    for (int p=0;p<16;p++) mu[p]=0.0f;
    for (int ki=0; ki<K; ki++){
        int iy = oy*2 + ki - PAD;
        if (iy < 0 || iy >= HIN) continue;
        for (int kj=0; kj<K; kj++){
            int ix = ox*2 + kj - PAD;
            if (ix < 0 || ix >= HIN) continue;
            int k = ki*K + kj;
            float coeff = a_in_g[((b*HIN+iy)*HIN+ix)*BC + c] * inv;
            const float* pm = &pose_in[((size_t)((b*HIN+iy)*HIN+ix))*(BC*16) + c*16];
            const float* Wk = &W[(size_t)(k*BC+c)*16];
            #pragma unroll
            for (int i=0;i<4;i++){
                #pragma unroll
                for (int l=0;l<4;l++){
                    float v = 0.0f;
                    #pragma unroll
                    for (int j=0;j<4;j++) v += pm[i*4+j]*Wk[j*4+l];
                    mu[i*4+l] += coeff*v;
                }
            }
        }
    }

    // pass 2: weighted variance
    float sg[16];
    #pragma unroll
    for (int p=0;p<16;p++) sg[p]=0.0f;
    for (int ki=0; ki<K; ki++){
        int iy = oy*2 + ki - PAD;
        if (iy < 0 || iy >= HIN) continue;
        for (int kj=0; kj<K; kj++){
            int ix = ox*2 + kj - PAD;
            if (ix < 0 || ix >= HIN) continue;
            int k = ki*K + kj;
            float coeff = a_in_g[((b*HIN+iy)*HIN+ix)*BC + c] * inv;
            const float* pm = &pose_in[((size_t)((b*HIN+iy)*HIN+ix))*(BC*16) + c*16];
            const float* Wk = &W[(size_t)(k*BC+c)*16];
            #pragma unroll
            for (int i=0;i<4;i++){
                #pragma unroll
                for (int l=0;l<4;l++){
                    float v = 0.0f;
                    #pragma unroll
                    for (int j=0;j<4;j++) v += pm[i*4+j]*Wk[j*4+l];
                    float d = v - mu[i*4+l];
                    sg[i*4+l] += coeff*d*d;
                }
            }
        }
    }

    float bu0 = bu[0], ba0 = ba[0];
    float cost = 0.0f;
    #pragma unroll
    for (int p=0;p<16;p++){
        sg[p] += EPSF;
        cost += bu0 + 0.5f*logf(sg[p]);
    }
    cost *= r_sum;
    float ao = sigmoidf_(LAMBDAF*(ba0 - cost));

    size_t o = (size_t)((b*HOUT+oy)*HOUT+ox);
    #pragma unroll
    for (int p=0;p<16;p++) pose_out[o*(BC*16) + c*16 + p] = mu[p];
    a_out_g[o*BC + c] = ao;
}

// ---------------- 1x1 conv caps with full EM (3 iters) ----------------
template<int BIN, int COUT>
__global__ void __launch_bounds__(256) cc_caps_kernel(
    const float* __restrict__ pose_in,  // (N, BIN*16)
    const float* __restrict__ a_g,      // (N, BIN)
    const float* __restrict__ W,        // (BIN, COUT, 4, 4)
    const float* __restrict__ bu, const float* __restrict__ ba,
    float* __restrict__ pose_out,       // (N, COUT*16)
    float* __restrict__ a_out_g)        // (N, COUT)
{
    static_assert(COUT*16 == 256, "block layout assumes COUT*16==256");
    __shared__ float s_pm[BIN*16];
    __shared__ float s_v [BIN*COUT*16];
    __shared__ float s_ain[BIN];
    __shared__ float s_r [BIN*COUT];
    __shared__ float s_rsum[COUT];
    __shared__ float s_mu[COUT*16];
    __shared__ float s_sig[COUT*16];
    __shared__ float s_i2 [COUT*16];
    __shared__ float s_cst[COUT];
    __shared__ float s_ao [COUT];
    __shared__ float s_lnap[BIN*COUT];

    int pos = blockIdx.x;
    int tid = threadIdx.x;

    for (int i=tid; i<BIN*16; i+=256) s_pm[i] = pose_in[(size_t)pos*BIN*16 + i];
    if (tid < BIN) s_ain[tid] = a_g[(size_t)pos*BIN + tid];
    for (int i=tid; i<BIN*COUT; i+=256) s_r[i] = 1.0f/COUT;
    __syncthreads();

    // votes
    for (int e=tid; e<BIN*COUT*16; e+=256){
        int p   = e & 15;
        int c0  = (e >> 4) % COUT;
        int bin = e / (COUT*16);
        int i = p >> 2, l = p & 3;
        float v = 0.0f;
        #pragma unroll
        for (int j=0;j<4;j++)
            v += s_pm[bin*16 + i*4 + j] * W[((bin*COUT + c0)*4 + j)*4 + l];
        s_v[e] = v;
    }
    __syncthreads();

    int c = tid >> 4, p = tid & 15;   // tid covers (c,p)
    for (int it=0; it<3; it++){
        if (tid < COUT){
            float s = 0.0f;
            #pragma unroll
            for (int bin=0; bin<BIN; bin++) s += s_r[bin*COUT+tid]*s_ain[bin];
            s_rsum[tid] = s;
        }
        __syncthreads();
        float inv = 1.0f/(s_rsum[c] + EPSF);
        float m = 0.0f;
        #pragma unroll
        for (int bin=0; bin<BIN; bin++)
            m += s_r[bin*COUT+c]*s_ain[bin] * s_v[(bin*COUT+c)*16 + p];
        m *= inv;
        s_mu[tid] = m;
        __syncthreads();
        float sg = 0.0f;
        #pragma unroll
        for (int bin=0; bin<BIN; bin++){
            float d = s_v[(bin*COUT+c)*16 + p] - m;
            sg += s_r[bin*COUT+c]*s_ain[bin]*d*d;
        }
        sg = sg*inv + EPSF;
        s_sig[tid] = sg;
        s_i2[tid]  = 0.5f/sg;
        __syncthreads();
        if (tid < COUT){
            float hls = 0.0f;
            #pragma unroll
            for (int q=0;q<16;q++) hls += 0.5f*logf(s_sig[tid*16+q]);
            float cost = (hls + 16.0f*bu[tid]) * s_rsum[tid];
            float ao = sigmoidf_(LAMBDAF*(ba[tid] - cost));
            s_ao[tid]  = ao;
            s_cst[tid] = -hls - 16.0f*LN2PI_HALF_F + logf(EPSF + ao);
        }
        __syncthreads();
        if (it < 2){
            if (tid < BIN*COUT){
                int bin = tid / COUT, c2 = tid % COUT;
                float acc = 0.0f;
                #pragma unroll
                for (int q=0;q<16;q++){
                    float d = s_v[(bin*COUT+c2)*16 + q] - s_mu[c2*16+q];
                    acc -= d*d*s_i2[c2*16+q];
                }
                s_lnap[tid] = acc + s_cst[c2];
            }
            __syncthreads();
            if (tid < BIN){
                float mx = -1e30f;
                #pragma unroll
                for (int c2=0;c2<COUT;c2++) mx = fmaxf(mx, s_lnap[tid*COUT+c2]);
                float ex[COUT]; float sum = 0.0f;
                #pragma unroll
                for (int c2=0;c2<COUT;c2++){ ex[c2]=expf(s_lnap[tid*COUT+c2]-mx); sum+=ex[c2]; }
                float isum = 1.0f/sum;
                #pragma unroll
                for (int c2=0;c2<COUT;c2++) s_r[tid*COUT+c2] = ex[c2]*isum;
            }
            __syncthreads();
        }
    }
    pose_out[(size_t)pos*COUT*16 + tid] = s_mu[tid];
    if (tid < COUT) a_out_g[(size_t)pos*COUT + tid] = s_ao[tid];
}

// ---------------- class caps: votes (with coordinate addition) ----------------
__global__ void __launch_bounds__(256) cls_votes_kernel(const float* __restrict__ W)
{
    int idx = blockIdx.x*256 + threadIdx.x;
    const int total = NB*CLS_BIN*CLS_E*PS;
    if (idx >= total) return;
    int p   = idx & 15;
    int e   = (idx >> 4) % CLS_E;
    int bin = (idx / (16*CLS_E)) % CLS_BIN;
    int b   = idx / (16*CLS_E*CLS_BIN);
    int d   = bin & 15;
    int ww  = (bin >> 4) & 7;
    int hh  = bin >> 7;
    int i = p >> 2, l = p & 3;
    const float* pm = &g_pose5[(size_t)b*(CLS_BIN*16) + (size_t)bin*16];
    float v = 0.0f;
    #pragma unroll
    for (int j=0;j<4;j++) v += pm[i*4+j]*W[((d*CLS_E+e)*4+j)*4+l];
    if (p == 0) v += (float)hh * 0.125f;
    if (p == 1) v += (float)ww * 0.125f;
    g_votes[idx] = v;
}

// ---------------- class caps: EM (Bin=1024, Cout=10), 1 block / batch ----------------
__global__ void __launch_bounds__(320) cls_em_kernel(
    const float* __restrict__ bu, const float* __restrict__ ba,
    float* __restrict__ out)
{
    __shared__ float s_ain[CLS_BIN];         // 4 KB
    __shared__ float s_r[CLS_BIN*CLS_E];     // 40 KB
    __shared__ float s_rsum[CLS_E];
    __shared__ float s_mu[CLS_E*16];
    __shared__ float s_sig[CLS_E*16];
    __shared__ float s_i2[CLS_E*16];
    __shared__ float s_cst[CLS_E];
    __shared__ float s_ao[CLS_E];

    int b = blockIdx.x;
    int tid = threadIdx.x;
    int warp = tid >> 5, lane = tid & 31;
    const float* vb = g_votes + (size_t)b*CLS_BIN*CLS_E*16;

    for (int i=tid; i<CLS_BIN; i+=320) s_ain[i] = g_a5[(size_t)b*CLS_BIN + i];
    for (int i=tid; i<CLS_BIN*CLS_E; i+=320) s_r[i] = 0.1f;
    __syncthreads();

    for (int it=0; it<3; it++){
        int e = warp;  // 10 warps, one per output capsule
        // r_sum
        float s = 0.0f;
        for (int bin=lane; bin<CLS_BIN; bin+=32) s += s_r[bin*CLS_E+e]*s_ain[bin];
        s = wred(s);
        if (lane == 0) s_rsum[e] = s;
        __syncthreads();
        float inv = 1.0f/(s_rsum[e] + EPSF);
        // mu
        float acc[16];
        #pragma unroll
        for (int q=0;q<16;q++) acc[q]=0.0f;
        for (int bin=lane; bin<CLS_BIN; bin+=32){
            float wgt = s_r[bin*CLS_E+e]*s_ain[bin]*inv;
            const float* vv = &vb[(size_t)(bin*CLS_E+e)*16];
            #pragma unroll
            for (int q=0;q<16;q++) acc[q] += wgt*vv[q];
        }
        #pragma unroll
        for (int q=0;q<16;q++) acc[q] = wred(acc[q]);
        if (lane == 0){
            #pragma unroll
            for (int q=0;q<16;q++) s_mu[e*16+q] = acc[q];
        }
        __syncthreads();
        // sigma
        float mul[16];
        #pragma unroll
        for (int q=0;q<16;q++){ mul[q]=s_mu[e*16+q]; acc[q]=0.0f; }
        for (int bin=lane; bin<CLS_BIN; bin+=32){
            float wgt = s_r[bin*CLS_E+e]*s_ain[bin]*inv;
            const float* vv = &vb[(size_t)(bin*CLS_E+e)*16];
            #pragma unroll
            for (int q=0;q<16;q++){ float d = vv[q]-mul[q]; acc[q] += wgt*d*d; }
        }
        #pragma unroll
        for (int q=0;q<16;q++) acc[q] = wred(acc[q]);
        if (lane == 0){
            #pragma unroll
            for (int q=0;q<16;q++) s_sig[e*16+q] = acc[q] + EPSF;
        }
        __syncthreads();
        if (tid < CLS_E*16) s_i2[tid] = 0.5f/s_sig[tid];
        if (tid < CLS_E){
            float hls = 0.0f;
            #pragma unroll
            for (int q=0;q<16;q++) hls += 0.5f*logf(s_sig[tid*16+q]);
            float cost = (hls + 16.0f*bu[tid]) * s_rsum[tid];
            float ao = sigmoidf_(LAMBDAF*(ba[tid] - cost));
            s_ao[tid]  = ao;
            s_cst[tid] = -hls - 16.0f*LN2PI_HALF_F + logf(EPSF + ao);
        }
        __syncthreads();
        if (it < 2){
            for (int bin=tid; bin<CLS_BIN; bin+=320){
                float lnap[CLS_E];
                float mx = -1e30f;
                #pragma unroll
                for (int e2=0; e2<CLS_E; e2++){
                    float a2 = 0.0f;
                    const float* vv = &vb[(size_t)(bin*CLS_E+e2)*16];
                    #pragma unroll
                    for (int q=0;q<16;q++){
                        float d = vv[q] - s_mu[e2*16+q];
                        a2 -= d*d*s_i2[e2*16+q];
                    }
                    lnap[e2] = a2 + s_cst[e2];
                    mx = fmaxf(mx, lnap[e2]);
                }
                float sum = 0.0f;
                #pragma unroll
                for (int e2=0;e2<CLS_E;e2++){ lnap[e2]=expf(lnap[e2]-mx); sum+=lnap[e2]; }
                float isum = 1.0f/sum;
                #pragma unroll
                for (int e2=0;e2<CLS_E;e2++) s_r[bin*CLS_E+e2] = lnap[e2]*isum;
            }
            __syncthreads();
        }
    }
    if (tid < CLS_E) out[b*CLS_E + tid] = s_ao[tid];
}

// ---------------- launch ----------------
extern "C" void kernel_launch(void* const* d_in, const int* in_sizes, int n_in,
                              void* d_out, int out_size)
{
    const float* x       = (const float*)d_in[0];
    const float* conv1_w = (const float*)d_in[1];
    const float* conv1_b = (const float*)d_in[2];
    const float* ppw     = (const float*)d_in[3];
    const float* ppb     = (const float*)d_in[4];
    const float* paw     = (const float*)d_in[5];
    const float* pab     = (const float*)d_in[6];
    const float* dw1_w   = (const float*)d_in[7];
    const float* dw1_bu  = (const float*)d_in[8];
    const float* dw1_ba  = (const float*)d_in[9];
    const float* cc1_w   = (const float*)d_in[10];
    const float* cc1_bu  = (const float*)d_in[11];
    const float* cc1_ba  = (const float*)d_in[12];
    const float* dw2_w   = (const float*)d_in[13];
    const float* dw2_bu  = (const float*)d_in[14];
    const float* dw2_ba  = (const float*)d_in[15];
    const float* cc2_w   = (const float*)d_in[16];
    const float* cc2_bu  = (const float*)d_in[17];
    const float* cc2_ba  = (const float*)d_in[18];
    const float* cls_w   = (const float*)d_in[19];
    const float* cls_bu  = (const float*)d_in[20];
    const float* cls_ba  = (const float*)d_in[21];
    float* out = (float*)d_out;

    // device symbol addresses (resolved once; cheap host calls, no allocation)
    float *p1, *a1, *p2, *a2, *p3, *a3, *p4, *a4;
    cudaGetSymbolAddress((void**)&p1, g_pose1);
    cudaGetSymbolAddress((void**)&a1, g_a1);
    cudaGetSymbolAddress((void**)&p2, g_pose2);
    cudaGetSymbolAddress((void**)&a2, g_a2);
    cudaGetSymbolAddress((void**)&p3, g_pose3);
    cudaGetSymbolAddress((void**)&a3, g_a3);
    cudaGetSymbolAddress((void**)&p4, g_pose4);
    cudaGetSymbolAddress((void**)&a4, g_a4);
    float *p5, *a5;
    cudaGetSymbolAddress((void**)&p5, g_pose5);
    cudaGetSymbolAddress((void**)&a5, g_a5);

    {   // 1: conv stem
        int total = NB*H1*H1*C1;
        conv1_kernel<<<(total+255)/256, 256>>>(x, conv1_w, conv1_b);
    }
    {   // 2: primary caps
        int total = NB*H1*H1*136;
        prim_kernel<<<(total+255)/256, 256>>>(ppw, ppb, paw, pab);
    }
    {   // 3: dw1 (K=7, pad=3, 30->15, 8 types)
        int total = NB*H2*H2*B1;
        dw_caps_kernel<7,3,H1,H2,B1><<<(total+127)/128, 128>>>(
            p1, a1, dw1_w, dw1_bu, dw1_ba, p2, a2);
    }
    {   // 4: cc1 (8 -> 16)
        int npos = NB*H2*H2;
        cc_caps_kernel<CC1_IN, CC1_OUT><<<npos, 256>>>(
            p2, a2, cc1_w, cc1_bu, cc1_ba, p3, a3);
    }
    {   // 5: dw2 (K=5, pad=2, 15->8, 16 types)
        int total = NB*H3*H3*CC1_OUT;
        dw_caps_kernel<5,2,H2,H3,CC1_OUT><<<(total+127)/128, 128>>>(
            p3, a3, dw2_w, dw2_bu, dw2_ba, p4, a4);
    }
    {   // 6: cc2 (16 -> 16)
        int npos = NB*H3*H3;
        cc_caps_kernel<CC2_IN, CC2_OUT><<<npos, 256>>>(
            p4, a4, cc2_w, cc2_bu, cc2_ba, p5, a5);
    }
    {   // 7: class votes
        int total = NB*CLS_BIN*CLS_E*PS;
        cls_votes_kernel<<<(total+255)/256, 256>>>(cls_w);
    }
    {   // 8: class EM
        cls_em_kernel<<<NB, 320>>>(cls_bu, cls_ba, out);
    }
}

// round 2
// speedup vs baseline: 3.9391x; 3.9391x over previous
#include <cuda_runtime.h>
#include <cuda_bf16.h>

#define EPSF 1e-8f
#define LAMBDAF 1e-3f
#define LN2PI_HALF_F 0.91893853320467274178f

// ---------------- network dims ----------------
#define NB 32
#define H0 64
#define H1 30
#define C1 64
#define B1 8
#define PS 16
#define H2 15
#define CC1_IN 8
#define CC1_OUT 16
#define H3 8
#define CC2_IN 16
#define CC2_OUT 16
#define CLS_D 16
#define CLS_E 10
#define CLS_BIN (H3*H3*CLS_D)   // 1024

// ---------------- scratch ----------------
__device__ float g_y    [NB*H1*H1*C1];
__device__ float g_pose1[NB*H1*H1*B1*PS];
__device__ float g_a1   [NB*H1*H1*B1];
__device__ float g_pose2[NB*H2*H2*B1*PS];
__device__ float g_a2   [NB*H2*H2*B1];
__device__ float g_pose3[NB*H2*H2*CC1_OUT*PS];
__device__ float g_a3   [NB*H2*H2*CC1_OUT];
__device__ float g_pose4[NB*H3*H3*CC1_OUT*PS];
__device__ float g_a4   [NB*H3*H3*CC1_OUT];
__device__ float g_pose5[NB*H3*H3*CC2_OUT*PS];
__device__ float g_a5   [NB*H3*H3*CC2_OUT];
__device__ float g_votes[NB*CLS_E*CLS_BIN*PS];      // layout (b,e,bin,p)
__device__ float g_r    [NB*CLS_E*CLS_BIN];         // layout (b,e,bin)
__device__ float g_S    [NB*CLS_E*33];              // S0, S1[16], S2[16]
__device__ float g_mu   [NB*CLS_E*16];
__device__ float g_i2   [NB*CLS_E*16];
__device__ float g_cst  [NB*CLS_E];

__device__ __forceinline__ float sigmoidf_(float x){ return 1.0f/(1.0f+expf(-x)); }

// ---------------- 1: conv stem + relu ----------------
__global__ void __launch_bounds__(256) conv1_kernel(
    const float* __restrict__ x, const float* __restrict__ w,
    const float* __restrict__ bias)
{
    int idx = blockIdx.x*256 + threadIdx.x;
    const int total = NB*H1*H1*C1;
    if (idx >= total) return;
    int co = idx & 63;
    int t  = idx >> 6;
    int ox = t % H1; t /= H1;
    int oy = t % H1; int b = t / H1;
    float s = bias[co];
    const float* xb = x + (size_t)b*H0*H0;
    #pragma unroll
    for (int kh=0; kh<5; kh++){
        const float* xr = xb + (oy*2+kh)*H0 + ox*2;
        #pragma unroll
        for (int kw=0; kw<5; kw++)
            s += xr[kw] * w[(kh*5+kw)*64 + co];
    }
    g_y[idx] = fmaxf(s, 0.0f);
}

// ---------------- 2: primary caps ----------------
__global__ void __launch_bounds__(256) prim_kernel(
    const float* __restrict__ Wp, const float* __restrict__ bp,
    const float* __restrict__ Wa, const float* __restrict__ ba)
{
    int idx = blockIdx.x*256 + threadIdx.x;
    const int total = NB*H1*H1*136;
    if (idx >= total) return;
    int d = idx % 136;
    int pos = idx / 136;
    const float* yy = g_y + (size_t)pos*C1;
    if (d < 128){
        float s = bp[d];
        #pragma unroll 8
        for (int c=0;c<C1;c++) s += yy[c]*Wp[c*128+d];
        g_pose1[(size_t)pos*128 + d] = s;
    } else {
        int da = d - 128;
        float s = ba[da];
        #pragma unroll 8
        for (int c=0;c<C1;c++) s += yy[c]*Wa[c*8+da];
        g_a1[(size_t)pos*8 + da] = sigmoidf_(s);
    }
}

// ---------------- depthwise caps: Cout=1 => single M-step, ONE pass ----------------
template<int K, int PAD, int HIN, int HOUT, int BC>
__global__ void __launch_bounds__(128) dw_caps_kernel(
    const float* __restrict__ pose_in,
    const float* __restrict__ a_in_g,
    const float* __restrict__ W,
    const float* __restrict__ bu, const float* __restrict__ ba,
    float* __restrict__ pose_out,
    float* __restrict__ a_out_g)
{
    int idx = blockIdx.x*128 + threadIdx.x;
    const int total = NB*HOUT*HOUT*BC;
    if (idx >= total) return;
    int c  = idx % BC;
    int t  = idx / BC;
    int ox = t % HOUT; t /= HOUT;
    int oy = t % HOUT; int b = t / HOUT;

    float S0 = 0.0f, T1[16], T2[16];
    #pragma unroll
    for (int p=0;p<16;p++){ T1[p]=0.0f; T2[p]=0.0f; }

    for (int ki=0; ki<K; ki++){
        int iy = oy*2 + ki - PAD;
        if (iy < 0 || iy >= HIN) continue;
        for (int kj=0; kj<K; kj++){
            int ix = ox*2 + kj - PAD;
            if (ix < 0 || ix >= HIN) continue;
            int k = ki*K + kj;
            float w = a_in_g[((b*HIN+iy)*HIN+ix)*BC + c];
            S0 += w;
            const float4* pm4 = (const float4*)&pose_in[((size_t)((b*HIN+iy)*HIN+ix))*(BC*16) + c*16];
            const float4* Wk4 = (const float4*)&W[(size_t)(k*BC+c)*16];
            float pm[16], Wk[16];
            #pragma unroll
            for (int q=0;q<4;q++){
                float4 v4 = pm4[q];
                pm[q*4+0]=v4.x; pm[q*4+1]=v4.y; pm[q*4+2]=v4.z; pm[q*4+3]=v4.w;
                float4 w4 = Wk4[q];
                Wk[q*4+0]=w4.x; Wk[q*4+1]=w4.y; Wk[q*4+2]=w4.z; Wk[q*4+3]=w4.w;
            }
            #pragma unroll
            for (int i=0;i<4;i++){
                #pragma unroll
                for (int l=0;l<4;l++){
                    float v = 0.0f;
                    #pragma unroll
                    for (int j=0;j<4;j++) v += pm[i*4+j]*Wk[j*4+l];
                    T1[i*4+l] += w*v;
                    T2[i*4+l] += w*v*v;
                }
            }
        }
    }

    float inv = 1.0f/(S0 + EPSF);
    float bu0 = bu[0], ba0 = ba[0];
    float cost = 0.0f;
    float mu[16];
    #pragma unroll
    for (int p=0;p<16;p++){
        float m = T1[p]*inv;
        mu[p] = m;
        float sg = fmaxf((T2[p] - 2.0f*m*T1[p] + m*m*S0)*inv, 0.0f) + EPSF;
        cost += bu0 + 0.5f*logf(sg);
    }
    cost *= S0;
    float ao = sigmoidf_(LAMBDAF*(ba0 - cost));

    size_t o = (size_t)((b*HOUT+oy)*HOUT+ox);
    float4* po = (float4*)&pose_out[o*(BC*16) + c*16];
    #pragma unroll
    for (int q=0;q<4;q++){
        float4 v4; v4.x=mu[q*4+0]; v4.y=mu[q*4+1]; v4.z=mu[q*4+2]; v4.w=mu[q*4+3];
        po[q] = v4;
    }
    a_out_g[o*BC + c] = ao;
}

// ---------------- 1x1 conv caps: warp-per-position, register EM ----------------
// lane = c (0..15) x half (0..1); each lane owns 8 pose components p = half*8+q
template<int BIN, int WPB>
__global__ void __launch_bounds__(WPB*32) cc_warp_kernel(
    const float* __restrict__ pose_in,   // (N, BIN*16)
    const float* __restrict__ a_g,       // (N, BIN)
    const float* __restrict__ W,         // (BIN,16,4,4)
    const float* __restrict__ bu, const float* __restrict__ ba,
    float* __restrict__ pose_out,        // (N, 256)
    float* __restrict__ a_out_g,         // (N, 16)
    int npos)
{
    __shared__ float sW[BIN*256];        // [bin][j][l][c] — conflict-free by c
    int tid = threadIdx.x;
    for (int i=tid; i<BIN*256; i+=WPB*32){
        int c2 = i & 15; int rest = i >> 4;
        int l = rest & 3; int j = (rest>>2)&3; int bin = rest>>4;
        sW[i] = W[(((size_t)bin*16 + c2)*4 + j)*4 + l];
    }
    __syncthreads();

    int warp = tid >> 5, lane = tid & 31;
    int pos = blockIdx.x*WPB + warp;
    if (pos >= npos) return;
    int c = lane & 15, half = lane >> 4;

    float v[BIN][8];
    float a_in[BIN], r[BIN];
    const float* pm = pose_in + (size_t)pos*BIN*16;
    const float* ag = a_g + (size_t)pos*BIN;
    #pragma unroll
    for (int bin=0; bin<BIN; bin++){
        a_in[bin] = ag[bin];
        r[bin] = 1.0f/16.0f;
        float pmr[8];
        #pragma unroll
        for (int j=0;j<8;j++) pmr[j] = pm[bin*16 + half*8 + j];
        #pragma unroll
        for (int q=0;q<8;q++){
            int i0 = q>>2, l = q&3;
            float s = 0.0f;
            #pragma unroll
            for (int j=0;j<4;j++)
                s += pmr[i0*4+j] * sW[(((bin*4+j)*4+l)<<4) + c];
            v[bin][q] = s;
        }
    }

    float buC = bu[c], baC = ba[c];
    float mu[8], sig[8], ao = 0.0f;

    #pragma unroll
    for (int it=0; it<3; it++){
        float rw[BIN]; float r_sum = 0.0f;
        #pragma unroll
        for (int bin=0;bin<BIN;bin++){ rw[bin] = r[bin]*a_in[bin]; r_sum += rw[bin]; }
        float inv = 1.0f/(r_sum + EPSF);
        #pragma unroll
        for (int q=0;q<8;q++){
            float m = 0.0f;
            #pragma unroll
            for (int bin=0;bin<BIN;bin++) m += rw[bin]*v[bin][q];
            mu[q] = m*inv;
        }
        float hls = 0.0f;
        #pragma unroll
        for (int q=0;q<8;q++){
            float s = 0.0f;
            #pragma unroll
            for (int bin=0;bin<BIN;bin++){
                float d = v[bin][q] - mu[q];
                s += rw[bin]*d*d;
            }
            float sg = s*inv + EPSF;
            sig[q] = sg;
            hls += 0.5f*logf(sg);
        }
        hls += __shfl_xor_sync(0xffffffffu, hls, 16);
        float cost = (hls + 16.0f*buC) * r_sum;
        ao = sigmoidf_(LAMBDAF*(baC - cost));
        if (it < 2){
            float cst = -hls - 16.0f*LN2PI_HALF_F + logf(EPSF + ao);
            float i2[8];
            #pragma unroll
            for (int q=0;q<8;q++) i2[q] = 0.5f/sig[q];
            #pragma unroll
            for (int bin=0;bin<BIN;bin++){
                float part = 0.0f;
                #pragma unroll
                for (int q=0;q<8;q++){
                    float d = v[bin][q] - mu[q];
                    part -= d*d*i2[q];
                }
                part += __shfl_xor_sync(0xffffffffu, part, 16);
                float lnap = part + cst;
                float mx = lnap;
                #pragma unroll
                for (int off=8; off; off>>=1)
                    mx = fmaxf(mx, __shfl_xor_sync(0xffffffffu, mx, off));
                float ex = expf(lnap - mx);
                float sum = ex;
                #pragma unroll
                for (int off=8; off; off>>=1)
                    sum += __shfl_xor_sync(0xffffffffu, sum, off);
                r[bin] = ex/sum;
            }
        }
    }

    size_t ob = (size_t)pos*256 + c*16 + half*8;
    #pragma unroll
    for (int q=0;q<8;q++) pose_out[ob+q] = mu[q];
    if (half == 0) a_out_g[(size_t)pos*16 + c] = ao;
}

// ---------------- class caps: votes, layout (b,e,bin,p) ----------------
__global__ void __launch_bounds__(256) cls_votes_kernel(const float* __restrict__ W)
{
    int idx = blockIdx.x*256 + threadIdx.x;
    const int total = NB*CLS_E*CLS_BIN*PS;
    if (idx >= total) return;
    int p   = idx & 15;
    int bin = (idx >> 4) % CLS_BIN;
    int e   = (idx / (16*CLS_BIN)) % CLS_E;
    int b   = idx / (16*CLS_BIN*CLS_E);
    int d   = bin & 15;
    int ww  = (bin >> 4) & 7;
    int hh  = bin >> 7;
    int i = p >> 2, l = p & 3;
    const float* pm = &g_pose5[(size_t)b*(CLS_BIN*16) + (size_t)bin*16];
    float v = 0.0f;
    #pragma unroll
    for (int j=0;j<4;j++) v += pm[i*4+j]*W[((d*CLS_E+e)*4+j)*4+l];
    if (p == 0) v += (float)hh * 0.125f;
    if (p == 1) v += (float)ww * 0.125f;
    g_votes[idx] = v;
}

// ---------------- class EM: reduce (S0, S1[16], S2[16]) per (b,e) ----------------
__global__ void __launch_bounds__(256) cls_reduce_kernel(int use_r)
{
    int be = blockIdx.x;                 // 0..NB*CLS_E-1
    int b = be / CLS_E;
    const float* vb = g_votes + (size_t)be*CLS_BIN*16;
    const float* rr = g_r + (size_t)be*CLS_BIN;
    const float* ab = g_a5 + (size_t)b*CLS_BIN;
    int tid = threadIdx.x, lane = tid & 31, warp = tid >> 5;

    float s0 = 0.0f, s1[16], s2[16];
    #pragma unroll
    for (int q=0;q<16;q++){ s1[q]=0.0f; s2[q]=0.0f; }

    for (int bin=tid; bin<CLS_BIN; bin+=256){
        float w = (use_r ? rr[bin] : 0.1f) * ab[bin];
        s0 += w;
        const float4* vv = (const float4*)(vb + (size_t)bin*16);
        #pragma unroll
        for (int q4=0;q4<4;q4++){
            float4 v4 = vv[q4];
            s1[q4*4+0] += w*v4.x; s2[q4*4+0] += w*v4.x*v4.x;
            s1[q4*4+1] += w*v4.y; s2[q4*4+1] += w*v4.y*v4.y;
            s1[q4*4+2] += w*v4.z; s2[q4*4+2] += w*v4.z*v4.z;
            s1[q4*4+3] += w*v4.w; s2[q4*4+3] += w*v4.w*v4.w;
        }
    }
    // warp reduce all 33 partials
    #pragma unroll
    for (int off=16; off; off>>=1){
        s0 += __shfl_xor_sync(0xffffffffu, s0, off);
        #pragma unroll
        for (int q=0;q<16;q++){
            s1[q] += __shfl_xor_sync(0xffffffffu, s1[q], off);
            s2[q] += __shfl_xor_sync(0xffffffffu, s2[q], off);
        }
    }
    __shared__ float red[8][33];
    if (lane == 0){
        red[warp][0] = s0;
        #pragma unroll
        for (int q=0;q<16;q++){ red[warp][1+q]=s1[q]; red[warp][17+q]=s2[q]; }
    }
    __syncthreads();
    if (tid < 33){
        float t = 0.0f;
        #pragma unroll
        for (int w8=0;w8<8;w8++) t += red[w8][tid];
        g_S[(size_t)be*33 + tid] = t;
    }
}

// ---------------- class EM: finalize mu/sigma/a_out/cst per (b,e) ----------------
__global__ void __launch_bounds__(160) cls_finalize_kernel(
    const float* __restrict__ bu, const float* __restrict__ ba,
    float* __restrict__ out, int last)
{
    int b = blockIdx.x;
    int tid = threadIdx.x;               // e*16+q
    int e = tid >> 4, q = tid & 15;
    int be = b*CLS_E + e;
    float S0 = g_S[(size_t)be*33];
    float S1 = g_S[(size_t)be*33 + 1 + q];
    float S2 = g_S[(size_t)be*33 + 17 + q];
    float inv = 1.0f/(S0 + EPSF);
    float m = S1*inv;
    float sg = fmaxf((S2 - 2.0f*m*S1 + m*m*S0)*inv, 0.0f) + EPSF;
    g_mu[(size_t)be*16 + q] = m;
    g_i2[(size_t)be*16 + q] = 0.5f/sg;
    float hl = 0.5f*logf(sg);
    #pragma unroll
    for (int off=8; off; off>>=1) hl += __shfl_xor_sync(0xffffffffu, hl, off);
    if (q == 0){
        float cost = (hl + 16.0f*bu[e]) * S0;
        float ao = sigmoidf_(LAMBDAF*(ba[e] - cost));
        g_cst[be] = -hl - 16.0f*LN2PI_HALF_F + logf(EPSF + ao);
        if (last) out[b*CLS_E + e] = ao;
    }
}

// ---------------- class EM: E step (softmax r over e) ----------------
__global__ void __launch_bounds__(256) cls_estep_kernel()
{
    int idx = blockIdx.x*256 + threadIdx.x;   // b*1024 + bin
    if (idx >= NB*CLS_BIN) return;
    int b = idx >> 10, bin = idx & 1023;
    float lnap[CLS_E];
    float mx = -1e30f;
    #pragma unroll
    for (int e=0;e<CLS_E;e++){
        int be = b*CLS_E + e;
        const float4* vv = (const float4*)(g_votes + ((size_t)be*CLS_BIN + bin)*16);
        const float4* mm = (const float4*)(g_mu + (size_t)be*16);
        const float4* ii = (const float4*)(g_i2 + (size_t)be*16);
        float acc = 0.0f;
        #pragma unroll
        for (int q4=0;q4<4;q4++){
            float4 v4 = vv[q4], m4 = mm[q4], i4 = ii[q4];
            float d0=v4.x-m4.x, d1=v4.y-m4.y, d2=v4.z-m4.z, d3=v4.w-m4.w;
            acc -= d0*d0*i4.x + d1*d1*i4.y + d2*d2*i4.z + d3*d3*i4.w;
        }
        lnap[e] = acc + g_cst[be];
        mx = fmaxf(mx, lnap[e]);
    }
    float sum = 0.0f;
    #pragma unroll
    for (int e=0;e<CLS_E;e++){ lnap[e] = expf(lnap[e]-mx); sum += lnap[e]; }
    float isum = 1.0f/sum;
    #pragma unroll
    for (int e=0;e<CLS_E;e++)
        g_r[((size_t)(b*CLS_E+e))*CLS_BIN + bin] = lnap[e]*isum;
}

// ---------------- launch ----------------
extern "C" void kernel_launch(void* const* d_in, const int* in_sizes, int n_in,
                              void* d_out, int out_size)
{
    const float* x       = (const float*)d_in[0];
    const float* conv1_w = (const float*)d_in[1];
    const float* conv1_b = (const float*)d_in[2];
    const float* ppw     = (const float*)d_in[3];
    const float* ppb     = (const float*)d_in[4];
    const float* paw     = (const float*)d_in[5];
    const float* pab     = (const float*)d_in[6];
    const float* dw1_w   = (const float*)d_in[7];
    const float* dw1_bu  = (const float*)d_in[8];
    const float* dw1_ba  = (const float*)d_in[9];
    const float* cc1_w   = (const float*)d_in[10];
    const float* cc1_bu  = (const float*)d_in[11];
    const float* cc1_ba  = (const float*)d_in[12];
    const float* dw2_w   = (const float*)d_in[13];
    const float* dw2_bu  = (const float*)d_in[14];
    const float* dw2_ba  = (const float*)d_in[15];
    const float* cc2_w   = (const float*)d_in[16];
    const float* cc2_bu  = (const float*)d_in[17];
    const float* cc2_ba  = (const float*)d_in[18];
    const float* cls_w   = (const float*)d_in[19];
    const float* cls_bu  = (const float*)d_in[20];
    const float* cls_ba  = (const float*)d_in[21];
    float* out = (float*)d_out;

    float *p1,*a1,*p2,*a2,*p3,*a3,*p4,*a4,*p5,*a5;
    cudaGetSymbolAddress((void**)&p1, g_pose1);
    cudaGetSymbolAddress((void**)&a1, g_a1);
    cudaGetSymbolAddress((void**)&p2, g_pose2);
    cudaGetSymbolAddress((void**)&a2, g_a2);
    cudaGetSymbolAddress((void**)&p3, g_pose3);
    cudaGetSymbolAddress((void**)&a3, g_a3);
    cudaGetSymbolAddress((void**)&p4, g_pose4);
    cudaGetSymbolAddress((void**)&a4, g_a4);
    cudaGetSymbolAddress((void**)&p5, g_pose5);
    cudaGetSymbolAddress((void**)&a5, g_a5);

    {   int total = NB*H1*H1*C1;
        conv1_kernel<<<(total+255)/256, 256>>>(x, conv1_w, conv1_b); }
    {   int total = NB*H1*H1*136;
        prim_kernel<<<(total+255)/256, 256>>>(ppw, ppb, paw, pab); }
    {   int total = NB*H2*H2*B1;
        dw_caps_kernel<7,3,H1,H2,B1><<<(total+127)/128, 128>>>(
            p1, a1, dw1_w, dw1_bu, dw1_ba, p2, a2); }
    {   int npos = NB*H2*H2;                 // 7200
        cc_warp_kernel<CC1_IN, 8><<<(npos+7)/8, 256>>>(
            p2, a2, cc1_w, cc1_bu, cc1_ba, p3, a3, npos); }
    {   int total = NB*H3*H3*CC1_OUT;
        dw_caps_kernel<5,2,H2,H3,CC1_OUT><<<(total+127)/128, 128>>>(
            p3, a3, dw2_w, dw2_bu, dw2_ba, p4, a4); }
    {   int npos = NB*H3*H3;                 // 2048
        cc_warp_kernel<CC2_IN, 4><<<(npos+3)/4, 128>>>(
            p4, a4, cc2_w, cc2_bu, cc2_ba, p5, a5, npos); }
    {   int total = NB*CLS_E*CLS_BIN*PS;
        cls_votes_kernel<<<(total+255)/256, 256>>>(cls_w); }
    // class EM: 3 iterations, split into small high-parallelism launches
    {
        int nbe = NB*CLS_E;                  // 320
        int nbins = NB*CLS_BIN;              // 32768
        // it 0
        cls_reduce_kernel<<<nbe, 256>>>(0);
        cls_finalize_kernel<<<NB, 160>>>(cls_bu, cls_ba, out, 0);
        cls_estep_kernel<<<(nbins+255)/256, 256>>>();
        // it 1
        cls_reduce_kernel<<<nbe, 256>>>(1);
        cls_finalize_kernel<<<NB, 160>>>(cls_bu, cls_ba, out, 0);
        cls_estep_kernel<<<(nbins+255)/256, 256>>>();
        // it 2 (final)
        cls_reduce_kernel<<<nbe, 256>>>(1);
        cls_finalize_kernel<<<NB, 160>>>(cls_bu, cls_ba, out, 1);
    }
}

// round 3
// speedup vs baseline: 4.3640x; 1.1079x over previous
#include <cuda_runtime.h>
#include <cuda_bf16.h>

#define EPSF 1e-8f
#define LAMBDAF 1e-3f
#define LN2PI_HALF_F 0.91893853320467274178f

// ---------------- network dims ----------------
#define NB 32
#define H0 64
#define H1 30
#define C1 64
#define B1 8
#define PS 16
#define H2 15
#define CC1_IN 8
#define CC1_OUT 16
#define H3 8
#define CC2_IN 16
#define CC2_OUT 16
#define CLS_D 16
#define CLS_E 10
#define CLS_BIN (H3*H3*CLS_D)   // 1024

// ---------------- scratch ----------------
__device__ float g_y    [NB*H1*H1*C1];
__device__ float g_pose1[NB*H1*H1*B1*PS];
__device__ float g_a1   [NB*H1*H1*B1];
__device__ float g_pose2[NB*H2*H2*B1*PS];
__device__ float g_a2   [NB*H2*H2*B1];
__device__ float g_pose3[NB*H2*H2*CC1_OUT*PS];
__device__ float g_a3   [NB*H2*H2*CC1_OUT];
__device__ float g_pose4[NB*H3*H3*CC1_OUT*PS];
__device__ float g_a4   [NB*H3*H3*CC1_OUT];
__device__ float g_pose5[NB*H3*H3*CC2_OUT*PS];
__device__ float g_a5   [NB*H3*H3*CC2_OUT];
__device__ float g_votes[NB*CLS_E*CLS_BIN*PS];      // (b,e,bin,p)
__device__ float g_r    [NB*CLS_E*CLS_BIN];         // (b,e,bin)
__device__ float g_mu   [NB*CLS_E*16];
__device__ float g_i2   [NB*CLS_E*16];
__device__ float g_cst  [NB*CLS_E];

__device__ __forceinline__ float sigmoidf_(float x){ return 1.0f/(1.0f+expf(-x)); }

// ---------------- 1: conv stem + relu ----------------
__global__ void __launch_bounds__(256) conv1_kernel(
    const float* __restrict__ x, const float* __restrict__ w,
    const float* __restrict__ bias)
{
    int idx = blockIdx.x*256 + threadIdx.x;
    const int total = NB*H1*H1*C1;
    if (idx >= total) return;
    int co = idx & 63;
    int t  = idx >> 6;
    int ox = t % H1; t /= H1;
    int oy = t % H1; int b = t / H1;
    float s = bias[co];
    const float* xb = x + (size_t)b*H0*H0;
    #pragma unroll
    for (int kh=0; kh<5; kh++){
        const float* xr = xb + (oy*2+kh)*H0 + ox*2;
        #pragma unroll
        for (int kw=0; kw<5; kw++)
            s += xr[kw] * w[(kh*5+kw)*64 + co];
    }
    g_y[idx] = fmaxf(s, 0.0f);
}

// ---------------- 2: primary caps ----------------
__global__ void __launch_bounds__(256) prim_kernel(
    const float* __restrict__ Wp, const float* __restrict__ bp,
    const float* __restrict__ Wa, const float* __restrict__ ba)
{
    int idx = blockIdx.x*256 + threadIdx.x;
    const int total = NB*H1*H1*136;
    if (idx >= total) return;
    int d = idx % 136;
    int pos = idx / 136;
    const float* yy = g_y + (size_t)pos*C1;
    if (d < 128){
        float s = bp[d];
        #pragma unroll 8
        for (int c=0;c<C1;c++) s += yy[c]*Wp[c*128+d];
        g_pose1[(size_t)pos*128 + d] = s;
    } else {
        int da = d - 128;
        float s = ba[da];
        #pragma unroll 8
        for (int c=0;c<C1;c++) s += yy[c]*Wa[c*8+da];
        g_a1[(size_t)pos*8 + da] = sigmoidf_(s);
    }
}

// ---------------- depthwise caps: smem-tiled, block per (b,c,row-tile) ----------------
template<int K, int PAD, int HIN, int HOUT, int BC, int OYT>
__global__ void __launch_bounds__(128) dw_tile_kernel(
    const float* __restrict__ pose_in,
    const float* __restrict__ a_in_g,
    const float* __restrict__ W,
    const float* __restrict__ bu, const float* __restrict__ ba,
    float* __restrict__ pose_out,
    float* __restrict__ a_out_g)
{
    constexpr int NT    = (HOUT + OYT - 1)/OYT;
    constexpr int IROWS = (OYT-1)*2 + K;
    constexpr int PLANE = IROWS*HIN;
    __shared__ float ps[16][PLANE];
    __shared__ float as[PLANE];
    __shared__ float ws[K*K*16];

    int blk = blockIdx.x;
    int tile = blk % NT;
    int c    = (blk / NT) % BC;
    int b    = blk / (NT*BC);
    int oy0  = tile*OYT;
    int iy0  = oy0*2 - PAD;
    int tid  = threadIdx.x;

    for (int i=tid; i<K*K*16; i+=128)
        ws[i] = W[(i>>4)*(BC*16) + c*16 + (i&15)];

    const float4* pbase = (const float4*)pose_in;
    for (int i=tid; i<PLANE*4; i+=128){
        int q4 = i & 3;
        int pos = i >> 2;
        int r = pos / HIN, ix = pos % HIN;
        int iy = iy0 + r;
        float4 v = make_float4(0.f,0.f,0.f,0.f);
        bool ok = (iy >= 0 && iy < HIN);
        if (ok)
            v = pbase[((size_t)((b*HIN+iy)*HIN+ix))*(BC*4) + c*4 + q4];
        ps[q4*4+0][pos]=v.x; ps[q4*4+1][pos]=v.y;
        ps[q4*4+2][pos]=v.z; ps[q4*4+3][pos]=v.w;
        if (q4 == 0)
            as[pos] = ok ? a_in_g[((b*HIN+iy)*HIN+ix)*BC + c] : 0.0f;
    }
    __syncthreads();

    if (tid >= OYT*HOUT) return;
    int oy_l = tid / HOUT, ox = tid % HOUT;
    int oy = oy0 + oy_l;
    if (oy >= HOUT) return;

    float S0 = 0.0f, T1[16], T2[16];
    #pragma unroll
    for (int p=0;p<16;p++){ T1[p]=0.0f; T2[p]=0.0f; }

    #pragma unroll
    for (int ki=0; ki<K; ki++){
        int iy = oy*2 + ki - PAD;
        if (iy < 0 || iy >= HIN) continue;
        int rr = iy - iy0;
        #pragma unroll
        for (int kj=0; kj<K; kj++){
            int ix = ox*2 + kj - PAD;
            if (ix < 0 || ix >= HIN) continue;
            int sp = rr*HIN + ix;
            float w = as[sp];
            S0 += w;
            float pm[16];
            #pragma unroll
            for (int q=0;q<16;q++) pm[q] = ps[q][sp];
            const float* Wk = &ws[(ki*K+kj)*16];
            #pragma unroll
            for (int i=0;i<4;i++){
                #pragma unroll
                for (int l=0;l<4;l++){
                    float v = 0.0f;
                    #pragma unroll
                    for (int j=0;j<4;j++) v += pm[i*4+j]*Wk[j*4+l];
                    T1[i*4+l] += w*v;
                    T2[i*4+l] += w*v*v;
                }
            }
        }
    }

    float inv = 1.0f/(S0 + EPSF);
    float bu0 = bu[0], ba0 = ba[0];
    float cost = 0.0f;
    float mu[16];
    #pragma unroll
    for (int p=0;p<16;p++){
        float m = T1[p]*inv;
        mu[p] = m;
        float sg = fmaxf((T2[p] - 2.0f*m*T1[p] + m*m*S0)*inv, 0.0f) + EPSF;
        cost += bu0 + 0.5f*logf(sg);
    }
    cost *= S0;
    float ao = sigmoidf_(LAMBDAF*(ba0 - cost));

    size_t o = (size_t)((b*HOUT+oy)*HOUT+ox);
    float4* po = (float4*)&pose_out[o*(BC*16) + c*16];
    #pragma unroll
    for (int q=0;q<4;q++){
        float4 v4; v4.x=mu[q*4+0]; v4.y=mu[q*4+1]; v4.z=mu[q*4+2]; v4.w=mu[q*4+3];
        po[q] = v4;
    }
    a_out_g[o*BC + c] = ao;
}

// ---------------- 1x1 conv caps: warp-per-position, smem votes, fused E/M ----------------
// lane = c (0..15) x half (0..1); lane owns components p = half*8+q
template<int BIN, int WPB>
__global__ void __launch_bounds__(WPB*32) cc_warp_kernel(
    const float* __restrict__ pose_in,   // (N, BIN*16)
    const float* __restrict__ a_g,       // (N, BIN)
    const float* __restrict__ W,         // (BIN,16,4,4)
    const float* __restrict__ bu, const float* __restrict__ ba,
    float* __restrict__ pose_out,        // (N, 256)
    float* __restrict__ a_out_g,         // (N, 16)
    int npos)
{
    __shared__ float sW[BIN*256];             // [bin][j][l][c]
    __shared__ float sv[WPB][BIN*8*32];       // [warp][(bin*8+q)*32+lane]
    int tid = threadIdx.x;
    for (int i=tid; i<BIN*256; i+=WPB*32){
        int c2 = i & 15; int rest = i >> 4;
        int l = rest & 3; int j = (rest>>2)&3; int bin = rest>>4;
        sW[i] = W[(((size_t)bin*16 + c2)*4 + j)*4 + l];
    }
    __syncthreads();

    int warp = tid >> 5, lane = tid & 31;
    int pos = blockIdx.x*WPB + warp;
    if (pos >= npos) return;
    int c = lane & 15, half = lane >> 4;
    float* v = sv[warp];

    const float* pm = pose_in + (size_t)pos*BIN*16;
    const float* ag = a_g + (size_t)pos*BIN;
    float a_in[BIN];
    float T1[8], T2[8]; float S0 = 0.0f;
    #pragma unroll
    for (int q=0;q<8;q++){ T1[q]=0.0f; T2[q]=0.0f; }

    // build votes + iter-0 M-step (r = 1/16)
    #pragma unroll
    for (int bin=0; bin<BIN; bin++){
        float a = ag[bin];
        a_in[bin] = a;
        float w = a * (1.0f/16.0f);
        S0 += w;
        const float4* pm4 = (const float4*)(pm + bin*16 + half*8);
        float4 p0 = pm4[0], p1 = pm4[1];
        float pmr[8] = {p0.x,p0.y,p0.z,p0.w,p1.x,p1.y,p1.z,p1.w};
        #pragma unroll
        for (int q=0;q<8;q++){
            int i0 = q>>2, l = q&3;
            float s = 0.0f;
            #pragma unroll
            for (int j=0;j<4;j++)
                s += pmr[i0*4+j] * sW[(((bin*4+j)*4+l)<<4) + c];
            v[(bin*8+q)*32 + lane] = s;
            T1[q] += w*s;
            T2[q] += w*s*s;
        }
    }

    float buC = bu[c], baC = ba[c];
    float mu[8], i2[8], cst = 0.0f, ao = 0.0f;
    {
        float inv = 1.0f/(S0 + EPSF);
        float hls = 0.0f;
        #pragma unroll
        for (int q=0;q<8;q++){
            float m = T1[q]*inv;
            mu[q] = m;
            float sg = fmaxf(T2[q]*inv - m*m, 0.0f) + EPSF;
            i2[q] = 0.5f/sg;
            hls += 0.5f*logf(sg);
        }
        hls += __shfl_xor_sync(0xffffffffu, hls, 16);
        float cost = (hls + 16.0f*buC) * S0;
        ao = sigmoidf_(LAMBDAF*(baC - cost));
        cst = -hls - 16.0f*LN2PI_HALF_F + logf(EPSF + ao);
    }

    // two fused E+M passes
    #pragma unroll
    for (int it=0; it<2; it++){
        float nT1[8], nT2[8]; float nS0 = 0.0f;
        #pragma unroll
        for (int q=0;q<8;q++){ nT1[q]=0.0f; nT2[q]=0.0f; }
        #pragma unroll
        for (int bin=0; bin<BIN; bin++){
            float vq[8];
            #pragma unroll
            for (int q=0;q<8;q++) vq[q] = v[(bin*8+q)*32 + lane];
            float part = 0.0f;
            #pragma unroll
            for (int q=0;q<8;q++){
                float d = vq[q] - mu[q];
                part -= d*d*i2[q];
            }
            part += __shfl_xor_sync(0xffffffffu, part, 16);
            float lnap = part + cst;
            float mx = lnap;
            #pragma unroll
            for (int off=8; off; off>>=1)
                mx = fmaxf(mx, __shfl_xor_sync(0xffffffffu, mx, off));
            float ex = expf(lnap - mx);
            float sum = ex;
            #pragma unroll
            for (int off=8; off; off>>=1)
                sum += __shfl_xor_sync(0xffffffffu, sum, off);
            float w = (ex/sum) * a_in[bin];
            nS0 += w;
            #pragma unroll
            for (int q=0;q<8;q++){
                nT1[q] += w*vq[q];
                nT2[q] += w*vq[q]*vq[q];
            }
        }
        float inv = 1.0f/(nS0 + EPSF);
        float hls = 0.0f;
        #pragma unroll
        for (int q=0;q<8;q++){
            float m = nT1[q]*inv;
            mu[q] = m;
            float sg = fmaxf(nT2[q]*inv - m*m, 0.0f) + EPSF;
            i2[q] = 0.5f/sg;
            hls += 0.5f*logf(sg);
        }
        hls += __shfl_xor_sync(0xffffffffu, hls, 16);
        float cost = (hls + 16.0f*buC) * nS0;
        ao = sigmoidf_(LAMBDAF*(baC - cost));
        if (it == 0) cst = -hls - 16.0f*LN2PI_HALF_F + logf(EPSF + ao);
    }

    size_t ob = (size_t)pos*256 + c*16 + half*8;
    #pragma unroll
    for (int q=0;q<8;q++) pose_out[ob+q] = mu[q];
    if (half == 0) a_out_g[(size_t)pos*16 + c] = ao;
}

// ---------------- class caps: votes, layout (b,e,bin,p) ----------------
__global__ void __launch_bounds__(256) cls_votes_kernel(const float* __restrict__ W)
{
    int idx = blockIdx.x*256 + threadIdx.x;
    const int total = NB*CLS_E*CLS_BIN*PS;
    if (idx >= total) return;
    int p   = idx & 15;
    int bin = (idx >> 4) % CLS_BIN;
    int e   = (idx / (16*CLS_BIN)) % CLS_E;
    int b   = idx / (16*CLS_BIN*CLS_E);
    int d   = bin & 15;
    int ww  = (bin >> 4) & 7;
    int hh  = bin >> 7;
    int i = p >> 2, l = p & 3;
    const float* pm = &g_pose5[(size_t)b*(CLS_BIN*16) + (size_t)bin*16];
    float v = 0.0f;
    #pragma unroll
    for (int j=0;j<4;j++) v += pm[i*4+j]*W[((d*CLS_E+e)*4+j)*4+l];
    if (p == 0) v += (float)hh * 0.125f;
    if (p == 1) v += (float)ww * 0.125f;
    g_votes[idx] = v;
}

// ---------------- class EM: fused reduce+finalize per (b,e) ----------------
__global__ void __launch_bounds__(256) cls_redfin_kernel(
    int use_r, const float* __restrict__ bu, const float* __restrict__ ba,
    float* __restrict__ out, int last)
{
    int be = blockIdx.x;
    int b = be / CLS_E, e = be % CLS_E;
    const float* vb = g_votes + (size_t)be*CLS_BIN*16;
    const float* rr = g_r + (size_t)be*CLS_BIN;
    const float* ab = g_a5 + (size_t)b*CLS_BIN;
    int tid = threadIdx.x, lane = tid & 31, warp = tid >> 5;

    float s0 = 0.0f, s1[16], s2[16];
    #pragma unroll
    for (int q=0;q<16;q++){ s1[q]=0.0f; s2[q]=0.0f; }

    for (int bin=tid; bin<CLS_BIN; bin+=256){
        float w = (use_r ? rr[bin] : 0.1f) * ab[bin];
        s0 += w;
        const float4* vv = (const float4*)(vb + (size_t)bin*16);
        #pragma unroll
        for (int q4=0;q4<4;q4++){
            float4 v4 = vv[q4];
            s1[q4*4+0] += w*v4.x; s2[q4*4+0] += w*v4.x*v4.x;
            s1[q4*4+1] += w*v4.y; s2[q4*4+1] += w*v4.y*v4.y;
            s1[q4*4+2] += w*v4.z; s2[q4*4+2] += w*v4.z*v4.z;
            s1[q4*4+3] += w*v4.w; s2[q4*4+3] += w*v4.w*v4.w;
        }
    }
    #pragma unroll
    for (int off=16; off; off>>=1){
        s0 += __shfl_xor_sync(0xffffffffu, s0, off);
        #pragma unroll
        for (int q=0;q<16;q++){
            s1[q] += __shfl_xor_sync(0xffffffffu, s1[q], off);
            s2[q] += __shfl_xor_sync(0xffffffffu, s2[q], off);
        }
    }
    __shared__ float red[8][33];
    __shared__ float smS[33];
    if (lane == 0){
        red[warp][0] = s0;
        #pragma unroll
        for (int q=0;q<16;q++){ red[warp][1+q]=s1[q]; red[warp][17+q]=s2[q]; }
    }
    __syncthreads();
    if (tid < 33){
        float t = 0.0f;
        #pragma unroll
        for (int w8=0;w8<8;w8++) t += red[w8][tid];
        smS[tid] = t;
    }
    __syncthreads();
    if (tid < 16){
        float S0 = smS[0];
        float S1 = smS[1+tid];
        float S2 = smS[17+tid];
        float inv = 1.0f/(S0 + EPSF);
        float m = S1*inv;
        float sg = fmaxf((S2 - 2.0f*m*S1 + m*m*S0)*inv, 0.0f) + EPSF;
        g_mu[(size_t)be*16 + tid] = m;
        g_i2[(size_t)be*16 + tid] = 0.5f/sg;
        float hl = 0.5f*logf(sg);
        #pragma unroll
        for (int off=8; off; off>>=1)
            hl += __shfl_xor_sync(0x0000ffffu, hl, off);
        if (tid == 0){
            float cost = (hl + 16.0f*bu[e]) * S0;
            float ao = sigmoidf_(LAMBDAF*(ba[e] - cost));
            g_cst[be] = -hl - 16.0f*LN2PI_HALF_F + logf(EPSF + ao);
            if (last) out[b*CLS_E + e] = ao;
        }
    }
}

// ---------------- class EM: E step ----------------
__global__ void __launch_bounds__(256) cls_estep_kernel()
{
    int idx = blockIdx.x*256 + threadIdx.x;
    if (idx >= NB*CLS_BIN) return;
    int b = idx >> 10, bin = idx & 1023;
    float lnap[CLS_E];
    float mx = -1e30f;
    #pragma unroll
    for (int e=0;e<CLS_E;e++){
        int be = b*CLS_E + e;
        const float4* vv = (const float4*)(g_votes + ((size_t)be*CLS_BIN + bin)*16);
        const float4* mm = (const float4*)(g_mu + (size_t)be*16);
        const float4* ii = (const float4*)(g_i2 + (size_t)be*16);
        float acc = 0.0f;
        #pragma unroll
        for (int q4=0;q4<4;q4++){
            float4 v4 = vv[q4], m4 = mm[q4], i4 = ii[q4];
            float d0=v4.x-m4.x, d1=v4.y-m4.y, d2=v4.z-m4.z, d3=v4.w-m4.w;
            acc -= d0*d0*i4.x + d1*d1*i4.y + d2*d2*i4.z + d3*d3*i4.w;
        }
        lnap[e] = acc + g_cst[be];
        mx = fmaxf(mx, lnap[e]);
    }
    float sum = 0.0f;
    #pragma unroll
    for (int e=0;e<CLS_E;e++){ lnap[e] = expf(lnap[e]-mx); sum += lnap[e]; }
    float isum = 1.0f/sum;
    #pragma unroll
    for (int e=0;e<CLS_E;e++)
        g_r[((size_t)(b*CLS_E+e))*CLS_BIN + bin] = lnap[e]*isum;
}

// ---------------- launch ----------------
extern "C" void kernel_launch(void* const* d_in, const int* in_sizes, int n_in,
                              void* d_out, int out_size)
{
    const float* x       = (const float*)d_in[0];
    const float* conv1_w = (const float*)d_in[1];
    const float* conv1_b = (const float*)d_in[2];
    const float* ppw     = (const float*)d_in[3];
    const float* ppb     = (const float*)d_in[4];
    const float* paw     = (const float*)d_in[5];
    const float* pab     = (const float*)d_in[6];
    const float* dw1_w   = (const float*)d_in[7];
    const float* dw1_bu  = (const float*)d_in[8];
    const float* dw1_ba  = (const float*)d_in[9];
    const float* cc1_w   = (const float*)d_in[10];
    const float* cc1_bu  = (const float*)d_in[11];
    const float* cc1_ba  = (const float*)d_in[12];
    const float* dw2_w   = (const float*)d_in[13];
    const float* dw2_bu  = (const float*)d_in[14];
    const float* dw2_ba  = (const float*)d_in[15];
    const float* cc2_w   = (const float*)d_in[16];
    const float* cc2_bu  = (const float*)d_in[17];
    const float* cc2_ba  = (const float*)d_in[18];
    const float* cls_w   = (const float*)d_in[19];
    const float* cls_bu  = (const float*)d_in[20];
    const float* cls_ba  = (const float*)d_in[21];
    float* out = (float*)d_out;

    float *p1,*a1,*p2,*a2,*p3,*a3,*p4,*a4,*p5,*a5;
    cudaGetSymbolAddress((void**)&p1, g_pose1);
    cudaGetSymbolAddress((void**)&a1, g_a1);
    cudaGetSymbolAddress((void**)&p2, g_pose2);
    cudaGetSymbolAddress((void**)&a2, g_a2);
    cudaGetSymbolAddress((void**)&p3, g_pose3);
    cudaGetSymbolAddress((void**)&a3, g_a3);
    cudaGetSymbolAddress((void**)&p4, g_pose4);
    cudaGetSymbolAddress((void**)&a4, g_a4);
    cudaGetSymbolAddress((void**)&p5, g_pose5);
    cudaGetSymbolAddress((void**)&a5, g_a5);

    {   int total = NB*H1*H1*C1;
        conv1_kernel<<<(total+255)/256, 256>>>(x, conv1_w, conv1_b); }
    {   int total = NB*H1*H1*136;
        prim_kernel<<<(total+255)/256, 256>>>(ppw, ppb, paw, pab); }
    {   // dw1: K=7 pad=3, 30->15, 8 types, 2 row-tiles of 8
        int grid = NB*B1*2;
        dw_tile_kernel<7,3,H1,H2,B1,8><<<grid, 128>>>(
            p1, a1, dw1_w, dw1_bu, dw1_ba, p2, a2); }
    {   int npos = NB*H2*H2;                 // 7200
        cc_warp_kernel<CC1_IN, 4><<<(npos+3)/4, 128>>>(
            p2, a2, cc1_w, cc1_bu, cc1_ba, p3, a3, npos); }
    {   // dw2: K=5 pad=2, 15->8, 16 types, 1 row-tile of 8
        int grid = NB*CC1_OUT*1;
        dw_tile_kernel<5,2,H2,H3,CC1_OUT,8><<<grid, 128>>>(
            p3, a3, dw2_w, dw2_bu, dw2_ba, p4, a4); }
    {   int npos = NB*H3*H3;                 // 2048
        cc_warp_kernel<CC2_IN, 2><<<(npos+1)/2, 64>>>(
            p4, a4, cc2_w, cc2_bu, cc2_ba, p5, a5, npos); }
    {   int total = NB*CLS_E*CLS_BIN*PS;
        cls_votes_kernel<<<(total+255)/256, 256>>>(cls_w); }
    {
        int nbe = NB*CLS_E;                  // 320
        int nbins = NB*CLS_BIN;              // 32768
        cls_redfin_kernel<<<nbe, 256>>>(0, cls_bu, cls_ba, out, 0);
        cls_estep_kernel<<<(nbins+255)/256, 256>>>();
        cls_redfin_kernel<<<nbe, 256>>>(1, cls_bu, cls_ba, out, 0);
        cls_estep_kernel<<<(nbins+255)/256, 256>>>();
        cls_redfin_kernel<<<nbe, 256>>>(1, cls_bu, cls_ba, out, 1);
    }
}

// round 4
// speedup vs baseline: 4.8200x; 1.1045x over previous
#include <cuda_runtime.h>
#include <cuda_bf16.h>

#define EPSF 1e-8f
#define LAMBDAF 1e-3f
#define LN2PI_HALF_F 0.91893853320467274178f

// ---------------- network dims ----------------
#define NB 32
#define H0 64
#define H1 30
#define C1 64
#define B1 8
#define PS 16
#define H2 15
#define CC1_IN 8
#define CC1_OUT 16
#define H3 8
#define CC2_IN 16
#define CC2_OUT 16
#define CLS_D 16
#define CLS_E 10
#define CLS_BIN (H3*H3*CLS_D)   // 1024

// ---------------- scratch ----------------
__device__ float g_y    [NB*H1*H1*C1];
__device__ float g_pose1[NB*H1*H1*B1*PS];
__device__ float g_a1   [NB*H1*H1*B1];
__device__ float g_pose2[NB*H2*H2*B1*PS];
__device__ float g_a2   [NB*H2*H2*B1];
__device__ float g_pose3[NB*H2*H2*CC1_OUT*PS];
__device__ float g_a3   [NB*H2*H2*CC1_OUT];
__device__ float g_pose4[NB*H3*H3*CC1_OUT*PS];
__device__ float g_a4   [NB*H3*H3*CC1_OUT];
__device__ float g_pose5[NB*H3*H3*CC2_OUT*PS];
__device__ float g_a5   [NB*H3*H3*CC2_OUT];
__device__ float g_votes[NB*CLS_E*CLS_BIN*PS];      // (b,e,bin,p)
__device__ float g_r    [NB*CLS_E*CLS_BIN];         // (b,e,bin)
__device__ float g_mu   [NB*CLS_E*16];
__device__ float g_i2   [NB*CLS_E*16];
__device__ float g_cst  [NB*CLS_E];

__device__ __forceinline__ float sigmoidf_(float x){ return 1.0f/(1.0f+expf(-x)); }

// ---------------- 1: conv stem + relu ----------------
__global__ void __launch_bounds__(256) conv1_kernel(
    const float* __restrict__ x, const float* __restrict__ w,
    const float* __restrict__ bias)
{
    int idx = blockIdx.x*256 + threadIdx.x;
    const int total = NB*H1*H1*C1;
    if (idx >= total) return;
    int co = idx & 63;
    int t  = idx >> 6;
    int ox = t % H1; t /= H1;
    int oy = t % H1; int b = t / H1;
    float s = bias[co];
    const float* xb = x + (size_t)b*H0*H0;
    #pragma unroll
    for (int kh=0; kh<5; kh++){
        const float* xr = xb + (oy*2+kh)*H0 + ox*2;
        #pragma unroll
        for (int kw=0; kw<5; kw++)
            s += xr[kw] * w[(kh*5+kw)*64 + co];
    }
    g_y[idx] = fmaxf(s, 0.0f);
}

// ---------------- 2: primary caps ----------------
__global__ void __launch_bounds__(256) prim_kernel(
    const float* __restrict__ Wp, const float* __restrict__ bp,
    const float* __restrict__ Wa, const float* __restrict__ ba)
{
    int idx = blockIdx.x*256 + threadIdx.x;
    const int total = NB*H1*H1*136;
    if (idx >= total) return;
    int d = idx % 136;
    int pos = idx / 136;
    const float* yy = g_y + (size_t)pos*C1;
    if (d < 128){
        float s = bp[d];
        #pragma unroll 8
        for (int c=0;c<C1;c++) s += yy[c]*Wp[c*128+d];
        g_pose1[(size_t)pos*128 + d] = s;
    } else {
        int da = d - 128;
        float s = ba[da];
        #pragma unroll 8
        for (int c=0;c<C1;c++) s += yy[c]*Wa[c*8+da];
        g_a1[(size_t)pos*8 + da] = sigmoidf_(s);
    }
}

// ---------------- depthwise caps: smem-tiled, block per (b,c,row-tile) ----------------
template<int K, int PAD, int HIN, int HOUT, int BC, int OYT>
__global__ void __launch_bounds__(128) dw_tile_kernel(
    const float* __restrict__ pose_in,
    const float* __restrict__ a_in_g,
    const float* __restrict__ W,
    const float* __restrict__ bu, const float* __restrict__ ba,
    float* __restrict__ pose_out,
    float* __restrict__ a_out_g)
{
    constexpr int NT    = (HOUT + OYT - 1)/OYT;
    constexpr int IROWS = (OYT-1)*2 + K;
    constexpr int PLANE = IROWS*HIN;
    __shared__ float ps[16][PLANE];
    __shared__ float as[PLANE];
    __shared__ float ws[K*K*16];

    int blk = blockIdx.x;
    int tile = blk % NT;
    int c    = (blk / NT) % BC;
    int b    = blk / (NT*BC);
    int oy0  = tile*OYT;
    int iy0  = oy0*2 - PAD;
    int tid  = threadIdx.x;

    for (int i=tid; i<K*K*16; i+=128)
        ws[i] = W[(i>>4)*(BC*16) + c*16 + (i&15)];

    const float4* pbase = (const float4*)pose_in;
    for (int i=tid; i<PLANE*4; i+=128){
        int q4 = i & 3;
        int pos = i >> 2;
        int r = pos / HIN, ix = pos % HIN;
        int iy = iy0 + r;
        float4 v = make_float4(0.f,0.f,0.f,0.f);
        bool ok = (iy >= 0 && iy < HIN);
        if (ok)
            v = pbase[((size_t)((b*HIN+iy)*HIN+ix))*(BC*4) + c*4 + q4];
        ps[q4*4+0][pos]=v.x; ps[q4*4+1][pos]=v.y;
        ps[q4*4+2][pos]=v.z; ps[q4*4+3][pos]=v.w;
        if (q4 == 0)
            as[pos] = ok ? a_in_g[((b*HIN+iy)*HIN+ix)*BC + c] : 0.0f;
    }
    __syncthreads();

    if (tid >= OYT*HOUT) return;
    int oy_l = tid / HOUT, ox = tid % HOUT;
    int oy = oy0 + oy_l;
    if (oy >= HOUT) return;

    float S0 = 0.0f, T1[16], T2[16];
    #pragma unroll
    for (int p=0;p<16;p++){ T1[p]=0.0f; T2[p]=0.0f; }

    #pragma unroll
    for (int ki=0; ki<K; ki++){
        int iy = oy*2 + ki - PAD;
        if (iy < 0 || iy >= HIN) continue;
        int rr = iy - iy0;
        #pragma unroll
        for (int kj=0; kj<K; kj++){
            int ix = ox*2 + kj - PAD;
            if (ix < 0 || ix >= HIN) continue;
            int sp = rr*HIN + ix;
            float w = as[sp];
            S0 += w;
            float pm[16];
            #pragma unroll
            for (int q=0;q<16;q++) pm[q] = ps[q][sp];
            const float* Wk = &ws[(ki*K+kj)*16];
            #pragma unroll
            for (int i=0;i<4;i++){
                #pragma unroll
                for (int l=0;l<4;l++){
                    float v = 0.0f;
                    #pragma unroll
                    for (int j=0;j<4;j++) v += pm[i*4+j]*Wk[j*4+l];
                    T1[i*4+l] += w*v;
                    T2[i*4+l] += w*v*v;
                }
            }
        }
    }

    float inv = 1.0f/(S0 + EPSF);
    float bu0 = bu[0], ba0 = ba[0];
    float cost = 0.0f;
    float mu[16];
    #pragma unroll
    for (int p=0;p<16;p++){
        float m = T1[p]*inv;
        mu[p] = m;
        float sg = fmaxf((T2[p] - 2.0f*m*T1[p] + m*m*S0)*inv, 0.0f) + EPSF;
        cost += bu0 + 0.5f*logf(sg);
    }
    cost *= S0;
    float ao = sigmoidf_(LAMBDAF*(ba0 - cost));

    size_t o = (size_t)((b*HOUT+oy)*HOUT+ox);
    float4* po = (float4*)&pose_out[o*(BC*16) + c*16];
    #pragma unroll
    for (int q=0;q<4;q++){
        float4 v4; v4.x=mu[q*4+0]; v4.y=mu[q*4+1]; v4.z=mu[q*4+2]; v4.w=mu[q*4+3];
        po[q] = v4;
    }
    a_out_g[o*BC + c] = ao;
}

// ---------------- 1x1 conv caps: warp-per-position, smem-transpose softmax ----------------
// lane = c (0..15) x half (0..1); lane owns components p = half*8+q
template<int BIN, int WPB>
__global__ void __launch_bounds__(WPB*32) cc_warp_kernel(
    const float* __restrict__ pose_in,   // (N, BIN*16)
    const float* __restrict__ a_g,       // (N, BIN)
    const float* __restrict__ W,         // (BIN,16,4,4)
    const float* __restrict__ bu, const float* __restrict__ ba,
    float* __restrict__ pose_out,        // (N, 256)
    float* __restrict__ a_out_g,         // (N, 16)
    int npos)
{
    __shared__ float sW[BIN*256];             // [bin][j][l][c]
    __shared__ float sv[WPB][BIN*8*32];       // votes [(bin*8+q)*32+lane]
    __shared__ float s_ln[WPB][BIN*17];       // lnap, stride-17 padded
    __shared__ float s_rw[WPB][BIN*17];       // r*a,  stride-17 padded
    __shared__ float s_ain[WPB][BIN];

    int tid = threadIdx.x;
    for (int i=tid; i<BIN*256; i+=WPB*32){
        int c2 = i & 15; int rest = i >> 4;
        int l = rest & 3; int j = (rest>>2)&3; int bin = rest>>4;
        sW[i] = W[(((size_t)bin*16 + c2)*4 + j)*4 + l];
    }
    __syncthreads();

    int warp = tid >> 5, lane = tid & 31;
    int pos = blockIdx.x*WPB + warp;
    if (pos >= npos) return;
    int c = lane & 15, half = lane >> 4;
    float* v   = sv[warp];
    float* lnp = s_ln[warp];
    float* rwp = s_rw[warp];
    float* ain = s_ain[warp];

    const float* pm = pose_in + (size_t)pos*BIN*16;
    const float* ag = a_g + (size_t)pos*BIN;
    if (half == 0 && c < BIN) ain[c] = ag[c];

    float T1[8], T2[8]; float S0 = 0.0f;
    #pragma unroll
    for (int q=0;q<8;q++){ T1[q]=0.0f; T2[q]=0.0f; }

    // build votes + iter-0 M-step (r = 1/16)
    #pragma unroll
    for (int bin=0; bin<BIN; bin++){
        float w = ag[bin] * (1.0f/16.0f);
        S0 += w;
        const float4* pm4 = (const float4*)(pm + bin*16 + half*8);
        float4 p0 = pm4[0], p1 = pm4[1];
        float pmr[8] = {p0.x,p0.y,p0.z,p0.w,p1.x,p1.y,p1.z,p1.w};
        #pragma unroll
        for (int q=0;q<8;q++){
            int i0 = q>>2, l = q&3;
            float s = 0.0f;
            #pragma unroll
            for (int j=0;j<4;j++)
                s += pmr[i0*4+j] * sW[(((bin*4+j)*4+l)<<4) + c];
            v[(bin*8+q)*32 + lane] = s;
            T1[q] += w*s;
            T2[q] += w*s*s;
        }
    }

    float buC = bu[c], baC = ba[c];
    float mu[8], i2[8], cst = 0.0f, ao = 0.0f;
    {
        float inv = 1.0f/(S0 + EPSF);
        float hls = 0.0f;
        #pragma unroll
        for (int q=0;q<8;q++){
            float m = T1[q]*inv;
            mu[q] = m;
            float sg = fmaxf(T2[q]*inv - m*m, 0.0f) + EPSF;
            i2[q] = 0.5f/sg;
            hls += 0.5f*logf(sg);
        }
        hls += __shfl_xor_sync(0xffffffffu, hls, 16);
        float cost = (hls + 16.0f*buC) * S0;
        ao = sigmoidf_(LAMBDAF*(baC - cost));
        cst = -hls - 16.0f*LN2PI_HALF_F + logf(EPSF + ao);
    }

    // two fused E+M passes; softmax over c done via smem transpose (lane=bin)
    #pragma unroll
    for (int it=0; it<2; it++){
        // Phase A: lnap[bin][c]
        float part[BIN];
        #pragma unroll
        for (int bin=0;bin<BIN;bin++){
            float p0 = 0.0f;
            #pragma unroll
            for (int q=0;q<8;q++){
                float d = v[(bin*8+q)*32 + lane] - mu[q];
                p0 -= d*d*i2[q];
            }
            part[bin] = p0;
        }
        #pragma unroll
        for (int bin=0;bin<BIN;bin++)
            part[bin] += __shfl_xor_sync(0xffffffffu, part[bin], 16);
        if (half == 0){
            #pragma unroll
            for (int bin=0;bin<BIN;bin++)
                lnp[bin*17 + c] = part[bin] + cst;
        }
        __syncwarp();
        // Phase B: softmax over c, lane = bin (register-resident, no shuffles)
        if (lane < BIN){
            float l16[16];
            float mx = -1e30f;
            #pragma unroll
            for (int c2=0;c2<16;c2++){ l16[c2] = lnp[lane*17 + c2]; mx = fmaxf(mx, l16[c2]); }
            float sum = 0.0f;
            #pragma unroll
            for (int c2=0;c2<16;c2++){ l16[c2] = expf(l16[c2]-mx); sum += l16[c2]; }
            float f = ain[lane]/sum;
            #pragma unroll
            for (int c2=0;c2<16;c2++) rwp[lane*17 + c2] = l16[c2]*f;
        }
        __syncwarp();
        // Phase C: M-step with new weights
        float nT1[8], nT2[8]; float nS0 = 0.0f;
        #pragma unroll
        for (int q=0;q<8;q++){ nT1[q]=0.0f; nT2[q]=0.0f; }
        #pragma unroll
        for (int bin=0;bin<BIN;bin++){
            float w = rwp[bin*17 + c];
            nS0 += w;
            #pragma unroll
            for (int q=0;q<8;q++){
                float vq = v[(bin*8+q)*32 + lane];
                nT1[q] += w*vq;
                nT2[q] += w*vq*vq;
            }
        }
        float inv = 1.0f/(nS0 + EPSF);
        float hls = 0.0f;
        #pragma unroll
        for (int q=0;q<8;q++){
            float m = nT1[q]*inv;
            mu[q] = m;
            float sg = fmaxf(nT2[q]*inv - m*m, 0.0f) + EPSF;
            i2[q] = 0.5f/sg;
            hls += 0.5f*logf(sg);
        }
        hls += __shfl_xor_sync(0xffffffffu, hls, 16);
        float cost = (hls + 16.0f*buC) * nS0;
        ao = sigmoidf_(LAMBDAF*(baC - cost));
        if (it == 0) cst = -hls - 16.0f*LN2PI_HALF_F + logf(EPSF + ao);
    }

    size_t ob = (size_t)pos*256 + c*16 + half*8;
    #pragma unroll
    for (int q=0;q<8;q++) pose_out[ob+q] = mu[q];
    if (half == 0) a_out_g[(size_t)pos*16 + c] = ao;
}

// ---------------- class EM iter0: fused votes + reduce + finalize per (b,e) ----------------
__global__ void __launch_bounds__(256) cls_vred_kernel(
    const float* __restrict__ W,
    const float* __restrict__ bu, const float* __restrict__ ba)
{
    int be = blockIdx.x;
    int b = be / CLS_E, e = be % CLS_E;
    int tid = threadIdx.x, lane = tid & 31, warp = tid >> 5;

    __shared__ float sw[16*17];              // [d][p], stride-17 padded
    if (tid < 256){
        int d = tid >> 4, p = tid & 15;
        int j = p >> 2, l = p & 3;
        sw[d*17 + p] = W[((d*CLS_E + e)*4 + j)*4 + l];
    }
    __syncthreads();

    float s0 = 0.0f, s1[16], s2[16];
    #pragma unroll
    for (int q=0;q<16;q++){ s1[q]=0.0f; s2[q]=0.0f; }

    for (int bin=tid; bin<CLS_BIN; bin+=256){
        int d  = bin & 15;
        int ww = (bin >> 4) & 7;
        int hh = bin >> 7;
        const float4* pm4 = (const float4*)(g_pose5 + ((size_t)b*CLS_BIN + bin)*16);
        float4 P0 = pm4[0], P1 = pm4[1], P2 = pm4[2], P3 = pm4[3];
        float pmv[16] = {P0.x,P0.y,P0.z,P0.w, P1.x,P1.y,P1.z,P1.w,
                         P2.x,P2.y,P2.z,P2.w, P3.x,P3.y,P3.z,P3.w};
        float w = 0.1f * g_a5[(size_t)b*CLS_BIN + bin];
        s0 += w;
        float4* vout = (float4*)(g_votes + ((size_t)be*CLS_BIN + bin)*16);
        const float* swd = &sw[d*17];
        #pragma unroll
        for (int i=0;i<4;i++){
            float vv[4];
            #pragma unroll
            for (int l=0;l<4;l++){
                float s = 0.0f;
                #pragma unroll
                for (int j=0;j<4;j++) s += pmv[i*4+j]*swd[j*4+l];
                vv[l] = s;
            }
            if (i == 0){ vv[0] += (float)hh*0.125f; vv[1] += (float)ww*0.125f; }
            float4 o4; o4.x=vv[0]; o4.y=vv[1]; o4.z=vv[2]; o4.w=vv[3];
            vout[i] = o4;
            #pragma unroll
            for (int l=0;l<4;l++){
                s1[i*4+l] += w*vv[l];
                s2[i*4+l] += w*vv[l]*vv[l];
            }
        }
    }

    #pragma unroll
    for (int off=16; off; off>>=1){
        s0 += __shfl_xor_sync(0xffffffffu, s0, off);
        #pragma unroll
        for (int q=0;q<16;q++){
            s1[q] += __shfl_xor_sync(0xffffffffu, s1[q], off);
            s2[q] += __shfl_xor_sync(0xffffffffu, s2[q], off);
        }
    }
    __shared__ float red[8][33];
    __shared__ float smS[33];
    if (lane == 0){
        red[warp][0] = s0;
        #pragma unroll
        for (int q=0;q<16;q++){ red[warp][1+q]=s1[q]; red[warp][17+q]=s2[q]; }
    }
    __syncthreads();
    if (tid < 33){
        float t = 0.0f;
        #pragma unroll
        for (int w8=0;w8<8;w8++) t += red[w8][tid];
        smS[tid] = t;
    }
    __syncthreads();
    if (tid < 16){
        float S0 = smS[0];
        float S1 = smS[1+tid];
        float S2 = smS[17+tid];
        float inv = 1.0f/(S0 + EPSF);
        float m = S1*inv;
        float sg = fmaxf((S2 - 2.0f*m*S1 + m*m*S0)*inv, 0.0f) + EPSF;
        g_mu[(size_t)be*16 + tid] = m;
        g_i2[(size_t)be*16 + tid] = 0.5f/sg;
        float hl = 0.5f*logf(sg);
        #pragma unroll
        for (int off=8; off; off>>=1)
            hl += __shfl_xor_sync(0x0000ffffu, hl, off);
        if (tid == 0){
            float cost = (hl + 16.0f*bu[e]) * S0;
            float ao = sigmoidf_(LAMBDAF*(ba[e] - cost));
            g_cst[be] = -hl - 16.0f*LN2PI_HALF_F + logf(EPSF + ao);
        }
    }
}

// ---------------- class EM: reduce+finalize (reads stored votes + r) ----------------
__global__ void __launch_bounds__(256) cls_redfin_kernel(
    const float* __restrict__ bu, const float* __restrict__ ba,
    float* __restrict__ out, int last)
{
    int be = blockIdx.x;
    int b = be / CLS_E, e = be % CLS_E;
    const float* vb = g_votes + (size_t)be*CLS_BIN*16;
    const float* rr = g_r + (size_t)be*CLS_BIN;
    const float* ab = g_a5 + (size_t)b*CLS_BIN;
    int tid = threadIdx.x, lane = tid & 31, warp = tid >> 5;

    float s0 = 0.0f, s1[16], s2[16];
    #pragma unroll
    for (int q=0;q<16;q++){ s1[q]=0.0f; s2[q]=0.0f; }

    for (int bin=tid; bin<CLS_BIN; bin+=256){
        float w = rr[bin] * ab[bin];
        s0 += w;
        const float4* vv = (const float4*)(vb + (size_t)bin*16);
        #pragma unroll
        for (int q4=0;q4<4;q4++){
            float4 v4 = vv[q4];
            s1[q4*4+0] += w*v4.x; s2[q4*4+0] += w*v4.x*v4.x;
            s1[q4*4+1] += w*v4.y; s2[q4*4+1] += w*v4.y*v4.y;
            s1[q4*4+2] += w*v4.z; s2[q4*4+2] += w*v4.z*v4.z;
            s1[q4*4+3] += w*v4.w; s2[q4*4+3] += w*v4.w*v4.w;
        }
    }
    #pragma unroll
    for (int off=16; off; off>>=1){
        s0 += __shfl_xor_sync(0xffffffffu, s0, off);
        #pragma unroll
        for (int q=0;q<16;q++){
            s1[q] += __shfl_xor_sync(0xffffffffu, s1[q], off);
            s2[q] += __shfl_xor_sync(0xffffffffu, s2[q], off);
        }
    }
    __shared__ float red[8][33];
    __shared__ float smS[33];
    if (lane == 0){
        red[warp][0] = s0;
        #pragma unroll
        for (int q=0;q<16;q++){ red[warp][1+q]=s1[q]; red[warp][17+q]=s2[q]; }
    }
    __syncthreads();
    if (tid < 33){
        float t = 0.0f;
        #pragma unroll
        for (int w8=0;w8<8;w8++) t += red[w8][tid];
        smS[tid] = t;
    }
    __syncthreads();
    if (tid < 16){
        float S0 = smS[0];
        float S1 = smS[1+tid];
        float S2 = smS[17+tid];
        float inv = 1.0f/(S0 + EPSF);
        float m = S1*inv;
        float sg = fmaxf((S2 - 2.0f*m*S1 + m*m*S0)*inv, 0.0f) + EPSF;
        g_mu[(size_t)be*16 + tid] = m;
        g_i2[(size_t)be*16 + tid] = 0.5f/sg;
        float hl = 0.5f*logf(sg);
        #pragma unroll
        for (int off=8; off; off>>=1)
            hl += __shfl_xor_sync(0x0000ffffu, hl, off);
        if (tid == 0){
            float cost = (hl + 16.0f*bu[e]) * S0;
            float ao = sigmoidf_(LAMBDAF*(ba[e] - cost));
            g_cst[be] = -hl - 16.0f*LN2PI_HALF_F + logf(EPSF + ao);
            if (last) out[b*CLS_E + e] = ao;
        }
    }
}

// ---------------- class EM: E step ----------------
__global__ void __launch_bounds__(256) cls_estep_kernel()
{
    int idx = blockIdx.x*256 + threadIdx.x;
    if (idx >= NB*CLS_BIN) return;
    int b = idx >> 10, bin = idx & 1023;
    float lnap[CLS_E];
    float mx = -1e30f;
    #pragma unroll
    for (int e=0;e<CLS_E;e++){
        int be = b*CLS_E + e;
        const float4* vv = (const float4*)(g_votes + ((size_t)be*CLS_BIN + bin)*16);
        const float4* mm = (const float4*)(g_mu + (size_t)be*16);
        const float4* ii = (const float4*)(g_i2 + (size_t)be*16);
        float acc = 0.0f;
        #pragma unroll
        for (int q4=0;q4<4;q4++){
            float4 v4 = vv[q4], m4 = mm[q4], i4 = ii[q4];
            float d0=v4.x-m4.x, d1=v4.y-m4.y, d2=v4.z-m4.z, d3=v4.w-m4.w;
            acc -= d0*d0*i4.x + d1*d1*i4.y + d2*d2*i4.z + d3*d3*i4.w;
        }
        lnap[e] = acc + g_cst[be];
        mx = fmaxf(mx, lnap[e]);
    }
    float sum = 0.0f;
    #pragma unroll
    for (int e=0;e<CLS_E;e++){ lnap[e] = expf(lnap[e]-mx); sum += lnap[e]; }
    float isum = 1.0f/sum;
    #pragma unroll
    for (int e=0;e<CLS_E;e++)
        g_r[((size_t)(b*CLS_E+e))*CLS_BIN + bin] = lnap[e]*isum;
}

// ---------------- launch ----------------
extern "C" void kernel_launch(void* const* d_in, const int* in_sizes, int n_in,
                              void* d_out, int out_size)
{
    const float* x       = (const float*)d_in[0];
    const float* conv1_w = (const float*)d_in[1];
    const float* conv1_b = (const float*)d_in[2];
    const float* ppw     = (const float*)d_in[3];
    const float* ppb     = (const float*)d_in[4];
    const float* paw     = (const float*)d_in[5];
    const float* pab     = (const float*)d_in[6];
    const float* dw1_w   = (const float*)d_in[7];
    const float* dw1_bu  = (const float*)d_in[8];
    const float* dw1_ba  = (const float*)d_in[9];
    const float* cc1_w   = (const float*)d_in[10];
    const float* cc1_bu  = (const float*)d_in[11];
    const float* cc1_ba  = (const float*)d_in[12];
    const float* dw2_w   = (const float*)d_in[13];
    const float* dw2_bu  = (const float*)d_in[14];
    const float* dw2_ba  = (const float*)d_in[15];
    const float* cc2_w   = (const float*)d_in[16];
    const float* cc2_bu  = (const float*)d_in[17];
    const float* cc2_ba  = (const float*)d_in[18];
    const float* cls_w   = (const float*)d_in[19];
    const float* cls_bu  = (const float*)d_in[20];
    const float* cls_ba  = (const float*)d_in[21];
    float* out = (float*)d_out;

    float *p1,*a1,*p2,*a2,*p3,*a3,*p4,*a4,*p5,*a5;
    cudaGetSymbolAddress((void**)&p1, g_pose1);
    cudaGetSymbolAddress((void**)&a1, g_a1);
    cudaGetSymbolAddress((void**)&p2, g_pose2);
    cudaGetSymbolAddress((void**)&a2, g_a2);
    cudaGetSymbolAddress((void**)&p3, g_pose3);
    cudaGetSymbolAddress((void**)&a3, g_a3);
    cudaGetSymbolAddress((void**)&p4, g_pose4);
    cudaGetSymbolAddress((void**)&a4, g_a4);
    cudaGetSymbolAddress((void**)&p5, g_pose5);
    cudaGetSymbolAddress((void**)&a5, g_a5);

    {   int total = NB*H1*H1*C1;
        conv1_kernel<<<(total+255)/256, 256>>>(x, conv1_w, conv1_b); }
    {   int total = NB*H1*H1*136;
        prim_kernel<<<(total+255)/256, 256>>>(ppw, ppb, paw, pab); }
    {   int grid = NB*B1*2;
        dw_tile_kernel<7,3,H1,H2,B1,8><<<grid, 128>>>(
            p1, a1, dw1_w, dw1_bu, dw1_ba, p2, a2); }
    {   int npos = NB*H2*H2;                 // 7200
        cc_warp_kernel<CC1_IN, 4><<<(npos+3)/4, 128>>>(
            p2, a2, cc1_w, cc1_bu, cc1_ba, p3, a3, npos); }
    {   int grid = NB*CC1_OUT*1;
        dw_tile_kernel<5,2,H2,H3,CC1_OUT,8><<<grid, 128>>>(
            p3, a3, dw2_w, dw2_bu, dw2_ba, p4, a4); }
    {   int npos = NB*H3*H3;                 // 2048
        cc_warp_kernel<CC2_IN, 4><<<(npos+3)/4, 128>>>(
            p4, a4, cc2_w, cc2_bu, cc2_ba, p5, a5, npos); }
    {
        int nbe = NB*CLS_E;                  // 320
        int nbins = NB*CLS_BIN;              // 32768
        cls_vred_kernel<<<nbe, 256>>>(cls_w, cls_bu, cls_ba);     // it0 (votes fused)
        cls_estep_kernel<<<(nbins+255)/256, 256>>>();
        cls_redfin_kernel<<<nbe, 256>>>(cls_bu, cls_ba, out, 0);  // it1
        cls_estep_kernel<<<(nbins+255)/256, 256>>>();
        cls_redfin_kernel<<<nbe, 256>>>(cls_bu, cls_ba, out, 1);  // it2
    }
}

// round 5
// speedup vs baseline: 4.8464x; 1.0055x over previous
#include <cuda_runtime.h>
#include <cuda_bf16.h>

#define EPSF 1e-8f
#define LAMBDAF 1e-3f
#define LN2PI_HALF_F 0.91893853320467274178f

// ---------------- network dims ----------------
#define NB 32
#define H0 64
#define H1 30
#define C1 64
#define B1 8
#define PS 16
#define H2 15
#define CC1_IN 8
#define CC1_OUT 16
#define H3 8
#define CC2_IN 16
#define CC2_OUT 16
#define CLS_D 16
#define CLS_E 10
#define CLS_BIN (H3*H3*CLS_D)   // 1024

// ---------------- scratch ----------------
__device__ float g_pose1[NB*H1*H1*B1*PS];
__device__ float g_a1   [NB*H1*H1*B1];
__device__ float g_pose2[NB*H2*H2*B1*PS];
__device__ float g_a2   [NB*H2*H2*B1];
__device__ float g_pose3[NB*H2*H2*CC1_OUT*PS];
__device__ float g_a3   [NB*H2*H2*CC1_OUT];
__device__ float g_pose4[NB*H3*H3*CC1_OUT*PS];
__device__ float g_a4   [NB*H3*H3*CC1_OUT];
__device__ float g_pose5[NB*H3*H3*CC2_OUT*PS];
__device__ float g_a5   [NB*H3*H3*CC2_OUT];
__device__ float g_votes[NB*CLS_E*CLS_BIN*PS];      // (b,e,bin,p)
__device__ float g_r    [NB*CLS_E*CLS_BIN];         // (b,e,bin)
__device__ float g_mu   [NB*CLS_E*16];
__device__ float g_i2   [NB*CLS_E*16];
__device__ float g_cst  [NB*CLS_E];

__device__ __forceinline__ float sigmoidf_(float x){ return 1.0f/(1.0f+expf(-x)); }

// ---------------- 1+2 fused: conv stem + relu + primary caps ----------------
// block = (b, ry): output rows {2ry, 2ry+1} x 30 cols = 60 positions
#define CP_SMEM_FLOATS (448 + 3900 + 1600 + 8192 + 512 + 128 + 8 + 64)
__global__ void __launch_bounds__(256) convprim_kernel(
    const float* __restrict__ x,  const float* __restrict__ wc,
    const float* __restrict__ bc,
    const float* __restrict__ Wp, const float* __restrict__ bp,
    const float* __restrict__ Wa, const float* __restrict__ ba)
{
    extern __shared__ float sm[];
    float* sx  = sm;              // 7*64   = 448
    float* sy  = sx  + 448;       // 60*65  = 3900 (padded)
    float* swc = sy  + 3900;      // 25*64  = 1600
    float* sWp = swc + 1600;      // 64*128 = 8192
    float* sWa = sWp + 8192;      // 64*8   = 512
    float* sbp = sWa + 512;       // 128
    float* sba = sbp + 128;       // 8
    float* sbc = sba + 8;         // 64

    int tid = threadIdx.x;
    int blk = blockIdx.x;
    int ry = blk % 15, b = blk / 15;

    for (int i=tid;i<1600;i+=256) swc[i]=wc[i];
    for (int i=tid;i<8192;i+=256) sWp[i]=Wp[i];
    for (int i=tid;i<512; i+=256) sWa[i]=Wa[i];
    if (tid<128) sbp[tid]=bp[tid];
    if (tid<8)   sba[tid]=ba[tid];
    if (tid<64)  sbc[tid]=bc[tid];
    const float* xb = x + (size_t)b*H0*H0;
    for (int i=tid;i<7*64;i+=256){
        int r=i>>6, cx=i&63;
        sx[i] = xb[(4*ry+r)*H0 + cx];
    }
    __syncthreads();

    // conv: 60 positions x 64 channels -> sy
    for (int i=tid;i<60*64;i+=256){
        int co = i & 63, pos = i >> 6;
        int oy_l = pos/30, ox = pos%30;
        float s = sbc[co];
        #pragma unroll
        for (int kh=0;kh<5;kh++){
            const float* xr = &sx[(oy_l*2+kh)*64 + ox*2];
            #pragma unroll
            for (int kw=0;kw<5;kw++)
                s += xr[kw]*swc[(kh*5+kw)*64+co];
        }
        sy[pos*65+co] = fmaxf(s,0.0f);
    }
    __syncthreads();

    // prim: 60 positions x 136 outputs
    for (int i=tid;i<60*136;i+=256){
        int d = i % 136, pos = i / 136;
        int oy = ry*2 + pos/30, ox = pos%30;
        size_t pg = ((size_t)(b*H1+oy))*H1 + ox;
        const float* yy = &sy[pos*65];
        if (d < 128){
            float s = sbp[d];
            #pragma unroll 16
            for (int c=0;c<64;c++) s += yy[c]*sWp[c*128+d];
            g_pose1[pg*128 + d] = s;
        } else {
            int da = d-128;
            float s = sba[da];
            #pragma unroll 16
            for (int c=0;c<64;c++) s += yy[c]*sWa[c*8+da];
            g_a1[pg*8+da] = sigmoidf_(s);
        }
    }
}

// ---------------- depthwise caps: smem-tiled, block per (b,c,row-tile) ----------------
template<int K, int PAD, int HIN, int HOUT, int BC, int OYT>
__global__ void __launch_bounds__(128) dw_tile_kernel(
    const float* __restrict__ pose_in,
    const float* __restrict__ a_in_g,
    const float* __restrict__ W,
    const float* __restrict__ bu, const float* __restrict__ ba,
    float* __restrict__ pose_out,
    float* __restrict__ a_out_g)
{
    constexpr int NT    = (HOUT + OYT - 1)/OYT;
    constexpr int IROWS = (OYT-1)*2 + K;
    constexpr int PLANE = IROWS*HIN;
    __shared__ float ps[16][PLANE];
    __shared__ float as[PLANE];
    __shared__ float ws[K*K*16];

    int blk = blockIdx.x;
    int tile = blk % NT;
    int c    = (blk / NT) % BC;
    int b    = blk / (NT*BC);
    int oy0  = tile*OYT;
    int iy0  = oy0*2 - PAD;
    int tid  = threadIdx.x;

    for (int i=tid; i<K*K*16; i+=128)
        ws[i] = W[(i>>4)*(BC*16) + c*16 + (i&15)];

    const float4* pbase = (const float4*)pose_in;
    for (int i=tid; i<PLANE*4; i+=128){
        int q4 = i & 3;
        int pos = i >> 2;
        int r = pos / HIN, ix = pos % HIN;
        int iy = iy0 + r;
        float4 v = make_float4(0.f,0.f,0.f,0.f);
        bool ok = (iy >= 0 && iy < HIN);
        if (ok)
            v = pbase[((size_t)((b*HIN+iy)*HIN+ix))*(BC*4) + c*4 + q4];
        ps[q4*4+0][pos]=v.x; ps[q4*4+1][pos]=v.y;
        ps[q4*4+2][pos]=v.z; ps[q4*4+3][pos]=v.w;
        if (q4 == 0)
            as[pos] = ok ? a_in_g[((b*HIN+iy)*HIN+ix)*BC + c] : 0.0f;
    }
    __syncthreads();

    if (tid >= OYT*HOUT) return;
    int oy_l = tid / HOUT, ox = tid % HOUT;
    int oy = oy0 + oy_l;
    if (oy >= HOUT) return;

    float S0 = 0.0f, T1[16], T2[16];
    #pragma unroll
    for (int p=0;p<16;p++){ T1[p]=0.0f; T2[p]=0.0f; }

    #pragma unroll
    for (int ki=0; ki<K; ki++){
        int iy = oy*2 + ki - PAD;
        if (iy < 0 || iy >= HIN) continue;
        int rr = iy - iy0;
        #pragma unroll
        for (int kj=0; kj<K; kj++){
            int ix = ox*2 + kj - PAD;
            if (ix < 0 || ix >= HIN) continue;
            int sp = rr*HIN + ix;
            float w = as[sp];
            S0 += w;
            float pm[16];
            #pragma unroll
            for (int q=0;q<16;q++) pm[q] = ps[q][sp];
            const float* Wk = &ws[(ki*K+kj)*16];
            #pragma unroll
            for (int i=0;i<4;i++){
                #pragma unroll
                for (int l=0;l<4;l++){
                    float v = 0.0f;
                    #pragma unroll
                    for (int j=0;j<4;j++) v += pm[i*4+j]*Wk[j*4+l];
                    T1[i*4+l] += w*v;
                    T2[i*4+l] += w*v*v;
                }
            }
        }
    }

    float inv = 1.0f/(S0 + EPSF);
    float bu0 = bu[0], ba0 = ba[0];
    float cost = 0.0f;
    float mu[16];
    #pragma unroll
    for (int p=0;p<16;p++){
        float m = T1[p]*inv;
        mu[p] = m;
        float sg = fmaxf((T2[p] - 2.0f*m*T1[p] + m*m*S0)*inv, 0.0f) + EPSF;
        cost += bu0 + 0.5f*logf(sg);
    }
    cost *= S0;
    float ao = sigmoidf_(LAMBDAF*(ba0 - cost));

    size_t o = (size_t)((b*HOUT+oy)*HOUT+ox);
    float4* po = (float4*)&pose_out[o*(BC*16) + c*16];
    #pragma unroll
    for (int q=0;q<4;q++){
        float4 v4; v4.x=mu[q*4+0]; v4.y=mu[q*4+1]; v4.z=mu[q*4+2]; v4.w=mu[q*4+3];
        po[q] = v4;
    }
    a_out_g[o*BC + c] = ao;
}

// ---------------- 1x1 conv caps: warp-per-position, smem-transpose softmax ----------------
template<int BIN, int WPB>
__global__ void __launch_bounds__(WPB*32) cc_warp_kernel(
    const float* __restrict__ pose_in,   // (N, BIN*16)
    const float* __restrict__ a_g,       // (N, BIN)
    const float* __restrict__ W,         // (BIN,16,4,4)
    const float* __restrict__ bu, const float* __restrict__ ba,
    float* __restrict__ pose_out,        // (N, 256)
    float* __restrict__ a_out_g,         // (N, 16)
    int npos)
{
    __shared__ float sW[BIN*256];             // [bin][j][l][c]
    __shared__ float sv[WPB][BIN*8*32];       // votes [(bin*8+q)*32+lane]
    __shared__ float s_ln[WPB][BIN*17];       // lnap / r*a, stride-17 padded
    __shared__ float s_rw[WPB][BIN*17];
    __shared__ float s_ain[WPB][BIN];

    int tid = threadIdx.x;
    for (int i=tid; i<BIN*256; i+=WPB*32){
        int c2 = i & 15; int rest = i >> 4;
        int l = rest & 3; int j = (rest>>2)&3; int bin = rest>>4;
        sW[i] = W[(((size_t)bin*16 + c2)*4 + j)*4 + l];
    }
    __syncthreads();

    int warp = tid >> 5, lane = tid & 31;
    int pos = blockIdx.x*WPB + warp;
    if (pos >= npos) return;
    int c = lane & 15, half = lane >> 4;
    float* v   = sv[warp];
    float* lnp = s_ln[warp];
    float* rwp = s_rw[warp];
    float* ain = s_ain[warp];

    const float* pm = pose_in + (size_t)pos*BIN*16;
    const float* ag = a_g + (size_t)pos*BIN;
    if (half == 0 && c < BIN) ain[c] = ag[c];

    float T1[8], T2[8]; float S0 = 0.0f;
    #pragma unroll
    for (int q=0;q<8;q++){ T1[q]=0.0f; T2[q]=0.0f; }

    #pragma unroll
    for (int bin=0; bin<BIN; bin++){
        float w = ag[bin] * (1.0f/16.0f);
        S0 += w;
        const float4* pm4 = (const float4*)(pm + bin*16 + half*8);
        float4 p0 = pm4[0], p1 = pm4[1];
        float pmr[8] = {p0.x,p0.y,p0.z,p0.w,p1.x,p1.y,p1.z,p1.w};
        #pragma unroll
        for (int q=0;q<8;q++){
            int i0 = q>>2, l = q&3;
            float s = 0.0f;
            #pragma unroll
            for (int j=0;j<4;j++)
                s += pmr[i0*4+j] * sW[(((bin*4+j)*4+l)<<4) + c];
            v[(bin*8+q)*32 + lane] = s;
            T1[q] += w*s;
            T2[q] += w*s*s;
        }
    }

    float buC = bu[c], baC = ba[c];
    float mu[8], i2[8], cst = 0.0f, ao = 0.0f;
    {
        float inv = 1.0f/(S0 + EPSF);
        float hls = 0.0f;
        #pragma unroll
        for (int q=0;q<8;q++){
            float m = T1[q]*inv;
            mu[q] = m;
            float sg = fmaxf(T2[q]*inv - m*m, 0.0f) + EPSF;
            i2[q] = 0.5f/sg;
            hls += 0.5f*logf(sg);
        }
        hls += __shfl_xor_sync(0xffffffffu, hls, 16);
        float cost = (hls + 16.0f*buC) * S0;
        ao = sigmoidf_(LAMBDAF*(baC - cost));
        cst = -hls - 16.0f*LN2PI_HALF_F + logf(EPSF + ao);
    }

    #pragma unroll
    for (int it=0; it<2; it++){
        float part[BIN];
        #pragma unroll
        for (int bin=0;bin<BIN;bin++){
            float p0 = 0.0f;
            #pragma unroll
            for (int q=0;q<8;q++){
                float d = v[(bin*8+q)*32 + lane] - mu[q];
                p0 -= d*d*i2[q];
            }
            part[bin] = p0;
        }
        #pragma unroll
        for (int bin=0;bin<BIN;bin++)
            part[bin] += __shfl_xor_sync(0xffffffffu, part[bin], 16);
        if (half == 0){
            #pragma unroll
            for (int bin=0;bin<BIN;bin++)
                lnp[bin*17 + c] = part[bin] + cst;
        }
        __syncwarp();
        if (lane < BIN){
            float l16[16];
            float mx = -1e30f;
            #pragma unroll
            for (int c2=0;c2<16;c2++){ l16[c2] = lnp[lane*17 + c2]; mx = fmaxf(mx, l16[c2]); }
            float sum = 0.0f;
            #pragma unroll
            for (int c2=0;c2<16;c2++){ l16[c2] = expf(l16[c2]-mx); sum += l16[c2]; }
            float f = ain[lane]/sum;
            #pragma unroll
            for (int c2=0;c2<16;c2++) rwp[lane*17 + c2] = l16[c2]*f;
        }
        __syncwarp();
        float nT1[8], nT2[8]; float nS0 = 0.0f;
        #pragma unroll
        for (int q=0;q<8;q++){ nT1[q]=0.0f; nT2[q]=0.0f; }
        #pragma unroll
        for (int bin=0;bin<BIN;bin++){
            float w = rwp[bin*17 + c];
            nS0 += w;
            #pragma unroll
            for (int q=0;q<8;q++){
                float vq = v[(bin*8+q)*32 + lane];
                nT1[q] += w*vq;
                nT2[q] += w*vq*vq;
            }
        }
        float inv = 1.0f/(nS0 + EPSF);
        float hls = 0.0f;
        #pragma unroll
        for (int q=0;q<8;q++){
            float m = nT1[q]*inv;
            mu[q] = m;
            float sg = fmaxf(nT2[q]*inv - m*m, 0.0f) + EPSF;
            i2[q] = 0.5f/sg;
            hls += 0.5f*logf(sg);
        }
        hls += __shfl_xor_sync(0xffffffffu, hls, 16);
        float cost = (hls + 16.0f*buC) * nS0;
        ao = sigmoidf_(LAMBDAF*(baC - cost));
        if (it == 0) cst = -hls - 16.0f*LN2PI_HALF_F + logf(EPSF + ao);
    }

    size_t ob = (size_t)pos*256 + c*16 + half*8;
    #pragma unroll
    for (int q=0;q<8;q++) pose_out[ob+q] = mu[q];
    if (half == 0) a_out_g[(size_t)pos*16 + c] = ao;
}

// ---------------- class EM iter0: fused votes + reduce + finalize per (b,e) ----------------
__global__ void __launch_bounds__(256) cls_vred_kernel(
    const float* __restrict__ W,
    const float* __restrict__ bu, const float* __restrict__ ba)
{
    int be = blockIdx.x;
    int b = be / CLS_E, e = be % CLS_E;
    int tid = threadIdx.x, lane = tid & 31, warp = tid >> 5;

    __shared__ float sw[16*17];
    if (tid < 256){
        int d = tid >> 4, p = tid & 15;
        int j = p >> 2, l = p & 3;
        sw[d*17 + p] = W[((d*CLS_E + e)*4 + j)*4 + l];
    }
    __syncthreads();

    float s0 = 0.0f, s1[16], s2[16];
    #pragma unroll
    for (int q=0;q<16;q++){ s1[q]=0.0f; s2[q]=0.0f; }

    for (int bin=tid; bin<CLS_BIN; bin+=256){
        int d  = bin & 15;
        int ww = (bin >> 4) & 7;
        int hh = bin >> 7;
        const float4* pm4 = (const float4*)(g_pose5 + ((size_t)b*CLS_BIN + bin)*16);
        float4 P0 = pm4[0], P1 = pm4[1], P2 = pm4[2], P3 = pm4[3];
        float pmv[16] = {P0.x,P0.y,P0.z,P0.w, P1.x,P1.y,P1.z,P1.w,
                         P2.x,P2.y,P2.z,P2.w, P3.x,P3.y,P3.z,P3.w};
        float w = 0.1f * g_a5[(size_t)b*CLS_BIN + bin];
        s0 += w;
        float4* vout = (float4*)(g_votes + ((size_t)be*CLS_BIN + bin)*16);
        const float* swd = &sw[d*17];
        #pragma unroll
        for (int i=0;i<4;i++){
            float vv[4];
            #pragma unroll
            for (int l=0;l<4;l++){
                float s = 0.0f;
                #pragma unroll
                for (int j=0;j<4;j++) s += pmv[i*4+j]*swd[j*4+l];
                vv[l] = s;
            }
            if (i == 0){ vv[0] += (float)hh*0.125f; vv[1] += (float)ww*0.125f; }
            float4 o4; o4.x=vv[0]; o4.y=vv[1]; o4.z=vv[2]; o4.w=vv[3];
            vout[i] = o4;
            #pragma unroll
            for (int l=0;l<4;l++){
                s1[i*4+l] += w*vv[l];
                s2[i*4+l] += w*vv[l]*vv[l];
            }
        }
    }

    #pragma unroll
    for (int off=16; off; off>>=1){
        s0 += __shfl_xor_sync(0xffffffffu, s0, off);
        #pragma unroll
        for (int q=0;q<16;q++){
            s1[q] += __shfl_xor_sync(0xffffffffu, s1[q], off);
            s2[q] += __shfl_xor_sync(0xffffffffu, s2[q], off);
        }
    }
    __shared__ float red[8][33];
    __shared__ float smS[33];
    if (lane == 0){
        red[warp][0] = s0;
        #pragma unroll
        for (int q=0;q<16;q++){ red[warp][1+q]=s1[q]; red[warp][17+q]=s2[q]; }
    }
    __syncthreads();
    if (tid < 33){
        float t = 0.0f;
        #pragma unroll
        for (int w8=0;w8<8;w8++) t += red[w8][tid];
        smS[tid] = t;
    }
    __syncthreads();
    if (tid < 16){
        float S0 = smS[0];
        float S1 = smS[1+tid];
        float S2 = smS[17+tid];
        float inv = 1.0f/(S0 + EPSF);
        float m = S1*inv;
        float sg = fmaxf((S2 - 2.0f*m*S1 + m*m*S0)*inv, 0.0f) + EPSF;
        g_mu[(size_t)be*16 + tid] = m;
        g_i2[(size_t)be*16 + tid] = 0.5f/sg;
        float hl = 0.5f*logf(sg);
        #pragma unroll
        for (int off=8; off; off>>=1)
            hl += __shfl_xor_sync(0x0000ffffu, hl, off);
        if (tid == 0){
            float cost = (hl + 16.0f*bu[e]) * S0;
            float ao = sigmoidf_(LAMBDAF*(ba[e] - cost));
            g_cst[be] = -hl - 16.0f*LN2PI_HALF_F + logf(EPSF + ao);
        }
    }
}

// ---------------- class EM: reduce+finalize (reads stored votes + r) ----------------
__global__ void __launch_bounds__(256) cls_redfin_kernel(
    const float* __restrict__ bu, const float* __restrict__ ba,
    float* __restrict__ out, int last)
{
    int be = blockIdx.x;
    int b = be / CLS_E, e = be % CLS_E;
    const float* vb = g_votes + (size_t)be*CLS_BIN*16;
    const float* rr = g_r + (size_t)be*CLS_BIN;
    const float* ab = g_a5 + (size_t)b*CLS_BIN;
    int tid = threadIdx.x, lane = tid & 31, warp = tid >> 5;

    float s0 = 0.0f, s1[16], s2[16];
    #pragma unroll
    for (int q=0;q<16;q++){ s1[q]=0.0f; s2[q]=0.0f; }

    for (int bin=tid; bin<CLS_BIN; bin+=256){
        float w = rr[bin] * ab[bin];
        s0 += w;
        const float4* vv = (const float4*)(vb + (size_t)bin*16);
        #pragma unroll
        for (int q4=0;q4<4;q4++){
            float4 v4 = vv[q4];
            s1[q4*4+0] += w*v4.x; s2[q4*4+0] += w*v4.x*v4.x;
            s1[q4*4+1] += w*v4.y; s2[q4*4+1] += w*v4.y*v4.y;
            s1[q4*4+2] += w*v4.z; s2[q4*4+2] += w*v4.z*v4.z;
            s1[q4*4+3] += w*v4.w; s2[q4*4+3] += w*v4.w*v4.w;
        }
    }
    #pragma unroll
    for (int off=16; off; off>>=1){
        s0 += __shfl_xor_sync(0xffffffffu, s0, off);
        #pragma unroll
        for (int q=0;q<16;q++){
            s1[q] += __shfl_xor_sync(0xffffffffu, s1[q], off);
            s2[q] += __shfl_xor_sync(0xffffffffu, s2[q], off);
        }
    }
    __shared__ float red[8][33];
    __shared__ float smS[33];
    if (lane == 0){
        red[warp][0] = s0;
        #pragma unroll
        for (int q=0;q<16;q++){ red[warp][1+q]=s1[q]; red[warp][17+q]=s2[q]; }
    }
    __syncthreads();
    if (tid < 33){
        float t = 0.0f;
        #pragma unroll
        for (int w8=0;w8<8;w8++) t += red[w8][tid];
        smS[tid] = t;
    }
    __syncthreads();
    if (tid < 16){
        float S0 = smS[0];
        float S1 = smS[1+tid];
        float S2 = smS[17+tid];
        float inv = 1.0f/(S0 + EPSF);
        float m = S1*inv;
        float sg = fmaxf((S2 - 2.0f*m*S1 + m*m*S0)*inv, 0.0f) + EPSF;
        g_mu[(size_t)be*16 + tid] = m;
        g_i2[(size_t)be*16 + tid] = 0.5f/sg;
        float hl = 0.5f*logf(sg);
        #pragma unroll
        for (int off=8; off; off>>=1)
            hl += __shfl_xor_sync(0x0000ffffu, hl, off);
        if (tid == 0){
            float cost = (hl + 16.0f*bu[e]) * S0;
            float ao = sigmoidf_(LAMBDAF*(ba[e] - cost));
            g_cst[be] = -hl - 16.0f*LN2PI_HALF_F + logf(EPSF + ao);
            if (last) out[b*CLS_E + e] = ao;
        }
    }
}

// ---------------- class EM: E step ----------------
__global__ void __launch_bounds__(256) cls_estep_kernel()
{
    int idx = blockIdx.x*256 + threadIdx.x;
    if (idx >= NB*CLS_BIN) return;
    int b = idx >> 10, bin = idx & 1023;
    float lnap[CLS_E];
    float mx = -1e30f;
    #pragma unroll
    for (int e=0;e<CLS_E;e++){
        int be = b*CLS_E + e;
        const float4* vv = (const float4*)(g_votes + ((size_t)be*CLS_BIN + bin)*16);
        const float4* mm = (const float4*)(g_mu + (size_t)be*16);
        const float4* ii = (const float4*)(g_i2 + (size_t)be*16);
        float acc = 0.0f;
        #pragma unroll
        for (int q4=0;q4<4;q4++){
            float4 v4 = vv[q4], m4 = mm[q4], i4 = ii[q4];
            float d0=v4.x-m4.x, d1=v4.y-m4.y, d2=v4.z-m4.z, d3=v4.w-m4.w;
            acc -= d0*d0*i4.x + d1*d1*i4.y + d2*d2*i4.z + d3*d3*i4.w;
        }
        lnap[e] = acc + g_cst[be];
        mx = fmaxf(mx, lnap[e]);
    }
    float sum = 0.0f;
    #pragma unroll
    for (int e=0;e<CLS_E;e++){ lnap[e] = expf(lnap[e]-mx); sum += lnap[e]; }
    float isum = 1.0f/sum;
    #pragma unroll
    for (int e=0;e<CLS_E;e++)
        g_r[((size_t)(b*CLS_E+e))*CLS_BIN + bin] = lnap[e]*isum;
}

// ---------------- launch ----------------
extern "C" void kernel_launch(void* const* d_in, const int* in_sizes, int n_in,
                              void* d_out, int out_size)
{
    const float* x       = (const float*)d_in[0];
    const float* conv1_w = (const float*)d_in[1];
    const float* conv1_b = (const float*)d_in[2];
    const float* ppw     = (const float*)d_in[3];
    const float* ppb     = (const float*)d_in[4];
    const float* paw     = (const float*)d_in[5];
    const float* pab     = (const float*)d_in[6];
    const float* dw1_w   = (const float*)d_in[7];
    const float* dw1_bu  = (const float*)d_in[8];
    const float* dw1_ba  = (const float*)d_in[9];
    const float* cc1_w   = (const float*)d_in[10];
    const float* cc1_bu  = (const float*)d_in[11];
    const float* cc1_ba  = (const float*)d_in[12];
    const float* dw2_w   = (const float*)d_in[13];
    const float* dw2_bu  = (const float*)d_in[14];
    const float* dw2_ba  = (const float*)d_in[15];
    const float* cc2_w   = (const float*)d_in[16];
    const float* cc2_bu  = (const float*)d_in[17];
    const float* cc2_ba  = (const float*)d_in[18];
    const float* cls_w   = (const float*)d_in[19];
    const float* cls_bu  = (const float*)d_in[20];
    const float* cls_ba  = (const float*)d_in[21];
    float* out = (float*)d_out;

    float *p1,*a1,*p2,*a2,*p3,*a3,*p4,*a4,*p5,*a5;
    cudaGetSymbolAddress((void**)&p1, g_pose1);
    cudaGetSymbolAddress((void**)&a1, g_a1);
    cudaGetSymbolAddress((void**)&p2, g_pose2);
    cudaGetSymbolAddress((void**)&a2, g_a2);
    cudaGetSymbolAddress((void**)&p3, g_pose3);
    cudaGetSymbolAddress((void**)&a3, g_a3);
    cudaGetSymbolAddress((void**)&p4, g_pose4);
    cudaGetSymbolAddress((void**)&a4, g_a4);
    cudaGetSymbolAddress((void**)&p5, g_pose5);
    cudaGetSymbolAddress((void**)&a5, g_a5);

    {   // fused conv stem + primary caps (dynamic smem ~58KB)
        const int smem_bytes = CP_SMEM_FLOATS * 4;
        cudaFuncSetAttribute(convprim_kernel,
                             cudaFuncAttributeMaxDynamicSharedMemorySize, smem_bytes);
        convprim_kernel<<<NB*15, 256, smem_bytes>>>(
            x, conv1_w, conv1_b, ppw, ppb, paw, pab);
    }
    {   int grid = NB*B1*2;
        dw_tile_kernel<7,3,H1,H2,B1,8><<<grid, 128>>>(
            p1, a1, dw1_w, dw1_bu, dw1_ba, p2, a2); }
    {   int npos = NB*H2*H2;                 // 7200
        cc_warp_kernel<CC1_IN, 4><<<(npos+3)/4, 128>>>(
            p2, a2, cc1_w, cc1_bu, cc1_ba, p3, a3, npos); }
    {   int grid = NB*CC1_OUT*1;
        dw_tile_kernel<5,2,H2,H3,CC1_OUT,8><<<grid, 128>>>(
            p3, a3, dw2_w, dw2_bu, dw2_ba, p4, a4); }
    {   int npos = NB*H3*H3;                 // 2048
        cc_warp_kernel<CC2_IN, 4><<<(npos+3)/4, 128>>>(
            p4, a4, cc2_w, cc2_bu, cc2_ba, p5, a5, npos); }
    {
        int nbe = NB*CLS_E;                  // 320
        int nbins = NB*CLS_BIN;              // 32768
        cls_vred_kernel<<<nbe, 256>>>(cls_w, cls_bu, cls_ba);
        cls_estep_kernel<<<(nbins+255)/256, 256>>>();
        cls_redfin_kernel<<<nbe, 256>>>(cls_bu, cls_ba, out, 0);
        cls_estep_kernel<<<(nbins+255)/256, 256>>>();
        cls_redfin_kernel<<<nbe, 256>>>(cls_bu, cls_ba, out, 1);
    }
}

// round 6
// speedup vs baseline: 5.3654x; 1.1071x over previous
#include <cuda_runtime.h>
#include <cuda_bf16.h>

#define EPSF 1e-8f
#define LAMBDAF 1e-3f
#define LN2PI_HALF_F 0.91893853320467274178f

typedef unsigned long long u64;
__device__ __forceinline__ u64 f2pk(float lo, float hi){
    u64 r; asm("mov.b64 %0,{%1,%2};" : "=l"(r) : "f"(lo), "f"(hi)); return r;
}
__device__ __forceinline__ void f2up(u64 v, float& lo, float& hi){
    asm("mov.b64 {%0,%1},%2;" : "=f"(lo), "=f"(hi) : "l"(v));
}
__device__ __forceinline__ u64 ffma2(u64 a, u64 b, u64 c){
    u64 d; asm("fma.rn.f32x2 %0,%1,%2,%3;" : "=l"(d) : "l"(a), "l"(b), "l"(c)); return d;
}
__device__ __forceinline__ u64 fmul2(u64 a, u64 b){
    u64 d; asm("mul.rn.f32x2 %0,%1,%2;" : "=l"(d) : "l"(a), "l"(b)); return d;
}

// ---------------- network dims ----------------
#define NB 32
#define H0 64
#define H1 30
#define C1 64
#define B1 8
#define PS 16
#define H2 15
#define CC1_IN 8
#define CC1_OUT 16
#define H3 8
#define CC2_IN 16
#define CC2_OUT 16
#define CLS_D 16
#define CLS_E 10
#define CLS_BIN (H3*H3*CLS_D)   // 1024

// ---------------- scratch ----------------
__device__ float g_pose1[NB*H1*H1*B1*PS];
__device__ float g_a1   [NB*H1*H1*B1];
__device__ float g_pose2[NB*H2*H2*B1*PS];
__device__ float g_a2   [NB*H2*H2*B1];
__device__ float g_pose3[NB*H2*H2*CC1_OUT*PS];
__device__ float g_a3   [NB*H2*H2*CC1_OUT];
__device__ float g_pose4[NB*H3*H3*CC1_OUT*PS];
__device__ float g_a4   [NB*H3*H3*CC1_OUT];
__device__ float g_pose5[NB*H3*H3*CC2_OUT*PS];
__device__ float g_a5   [NB*H3*H3*CC2_OUT];
__device__ float g_votes[NB*CLS_E*CLS_BIN*PS];
__device__ float g_r    [NB*CLS_E*CLS_BIN];
__device__ float g_mu   [NB*CLS_E*16];
__device__ float g_i2   [NB*CLS_E*16];
__device__ float g_cst  [NB*CLS_E];

__device__ __forceinline__ float sigmoidf_(float x){ return 1.0f/(1.0f+expf(-x)); }

// ---------------- 1+2 fused: conv stem + relu + primary caps (f32x2) ----------------
#define CP_SMEM_FLOATS (448 + 3900 + 1600 + 8192 + 512 + 128 + 8 + 64)
__global__ void __launch_bounds__(256) convprim_kernel(
    const float* __restrict__ x,  const float* __restrict__ wc,
    const float* __restrict__ bc,
    const float* __restrict__ Wp, const float* __restrict__ bp,
    const float* __restrict__ Wa, const float* __restrict__ ba)
{
    extern __shared__ float sm[];
    float* sx  = sm;              // 7*64   = 448
    float* sy  = sx  + 448;       // 60*65  = 3900 (padded)
    float* swc = sy  + 3900;      // 25*64  = 1600 (elem offset 4348, even)
    float* sWp = swc + 1600;      // 64*128 = 8192 (even)
    float* sWa = sWp + 8192;      // 64*8   = 512  (even)
    float* sbp = sWa + 512;
    float* sba = sbp + 128;
    float* sbc = sba + 8;

    int tid = threadIdx.x;
    int blk = blockIdx.x;
    int ry = blk % 15, b = blk / 15;

    for (int i=tid;i<1600;i+=256) swc[i]=wc[i];
    for (int i=tid;i<8192;i+=256) sWp[i]=Wp[i];
    for (int i=tid;i<512; i+=256) sWa[i]=Wa[i];
    if (tid<128) sbp[tid]=bp[tid];
    if (tid<8)   sba[tid]=ba[tid];
    if (tid<64)  sbc[tid]=bc[tid];
    const float* xb = x + (size_t)b*H0*H0;
    for (int i=tid;i<7*64;i+=256){
        int r=i>>6, cx=i&63;
        sx[i] = xb[(4*ry+r)*H0 + cx];
    }
    __syncthreads();

    // conv: 60 positions x 16 channel-quads
    for (int i=tid;i<60*16;i+=256){
        int c4 = (i & 15)*4, pos = i >> 4;
        int oy_l = pos/30, ox = pos%30;
        u64 a0 = f2pk(sbc[c4],   sbc[c4+1]);
        u64 a1 = f2pk(sbc[c4+2], sbc[c4+3]);
        #pragma unroll
        for (int kh=0;kh<5;kh++){
            const float* xr = &sx[(oy_l*2+kh)*64 + ox*2];
            #pragma unroll
            for (int kw=0;kw<5;kw++){
                float xv = xr[kw];
                u64 x2 = f2pk(xv,xv);
                const u64* w2 = (const u64*)&swc[(kh*5+kw)*64 + c4];
                a0 = ffma2(x2, w2[0], a0);
                a1 = ffma2(x2, w2[1], a1);
            }
        }
        float v0,v1,v2,v3;
        f2up(a0,v0,v1); f2up(a1,v2,v3);
        float* yo = &sy[pos*65 + c4];
        yo[0]=fmaxf(v0,0.f); yo[1]=fmaxf(v1,0.f);
        yo[2]=fmaxf(v2,0.f); yo[3]=fmaxf(v3,0.f);
    }
    __syncthreads();

    // prim: 60 positions x 34 output-quads (32 pose + 2 act)
    for (int i=tid;i<60*34;i+=256){
        int qd = i % 34, pos = i / 34;
        int oy = ry*2 + pos/30, ox = pos%30;
        size_t pg = ((size_t)(b*H1+oy))*H1 + ox;
        const float* yy = &sy[pos*65];
        if (qd < 32){
            int d0 = qd*4;
            u64 a0 = f2pk(sbp[d0],   sbp[d0+1]);
            u64 a1 = f2pk(sbp[d0+2], sbp[d0+3]);
            #pragma unroll 8
            for (int c=0;c<64;c++){
                float yv = yy[c];
                u64 y2 = f2pk(yv,yv);
                const u64* w2 = (const u64*)&sWp[c*128 + d0];
                a0 = ffma2(y2, w2[0], a0);
                a1 = ffma2(y2, w2[1], a1);
            }
            float v0,v1,v2,v3;
            f2up(a0,v0,v1); f2up(a1,v2,v3);
            float4 o4; o4.x=v0; o4.y=v1; o4.z=v2; o4.w=v3;
            *(float4*)&g_pose1[pg*128 + d0] = o4;
        } else {
            int da0 = (qd-32)*4;
            u64 a0 = f2pk(sba[da0],   sba[da0+1]);
            u64 a1 = f2pk(sba[da0+2], sba[da0+3]);
            #pragma unroll 8
            for (int c=0;c<64;c++){
                float yv = yy[c];
                u64 y2 = f2pk(yv,yv);
                const u64* w2 = (const u64*)&sWa[c*8 + da0];
                a0 = ffma2(y2, w2[0], a0);
                a1 = ffma2(y2, w2[1], a1);
            }
            float v0,v1,v2,v3;
            f2up(a0,v0,v1); f2up(a1,v2,v3);
            float4 o4;
            o4.x=sigmoidf_(v0); o4.y=sigmoidf_(v1);
            o4.z=sigmoidf_(v2); o4.w=sigmoidf_(v3);
            *(float4*)&g_a1[pg*8 + da0] = o4;
        }
    }
}

// ---------------- depthwise caps: smem-tiled, half-split threads, f32x2 ----------------
template<int K, int PAD, int HIN, int HOUT, int BC, int OYT, int BLK>
__global__ void __launch_bounds__(BLK) dw_tile_kernel(
    const float* __restrict__ pose_in,
    const float* __restrict__ a_in_g,
    const float* __restrict__ W,
    const float* __restrict__ bu, const float* __restrict__ ba,
    float* __restrict__ pose_out,
    float* __restrict__ a_out_g)
{
    constexpr int NT    = (HOUT + OYT - 1)/OYT;
    constexpr int IROWS = (OYT-1)*2 + K;
    constexpr int PLANE = IROWS*HIN;
    constexpr int NPOS  = OYT*HOUT;
    __shared__ float ps[16][PLANE];
    __shared__ float as[PLANE];
    __shared__ __align__(16) float ws[K*K*16];
    __shared__ float s_h[NPOS];

    int blk = blockIdx.x;
    int tile = blk % NT;
    int c    = (blk / NT) % BC;
    int b    = blk / (NT*BC);
    int oy0  = tile*OYT;
    int iy0  = oy0*2 - PAD;
    int tid  = threadIdx.x;

    for (int i=tid; i<K*K*16; i+=BLK)
        ws[i] = W[(i>>4)*(BC*16) + c*16 + (i&15)];

    const float4* pbase = (const float4*)pose_in;
    for (int i=tid; i<PLANE*4; i+=BLK){
        int q4 = i & 3;
        int pos = i >> 2;
        int r = pos / HIN, ix = pos % HIN;
        int iy = iy0 + r;
        float4 v = make_float4(0.f,0.f,0.f,0.f);
        bool ok = (iy >= 0 && iy < HIN);
        if (ok)
            v = pbase[((size_t)((b*HIN+iy)*HIN+ix))*(BC*4) + c*4 + q4];
        ps[q4*4+0][pos]=v.x; ps[q4*4+1][pos]=v.y;
        ps[q4*4+2][pos]=v.z; ps[q4*4+3][pos]=v.w;
        if (q4 == 0)
            as[pos] = ok ? a_in_g[((b*HIN+iy)*HIN+ix)*BC + c] : 0.0f;
    }
    __syncthreads();

    bool act = tid < 2*NPOS;
    int half = 0, pos_t = 0, oy = 0, ox = 0;
    if (act){
        half  = (tid >= NPOS) ? 1 : 0;
        pos_t = tid - half*NPOS;
        int oy_l = pos_t / HOUT;
        ox = pos_t % HOUT;
        oy = oy0 + oy_l;
        if (oy >= HOUT) act = false;
    }

    float S0 = 0.0f;
    u64 T1p[4], T2p[4];
    #pragma unroll
    for (int a=0;a<4;a++){ T1p[a]=f2pk(0.f,0.f); T2p[a]=f2pk(0.f,0.f); }

    if (act){
        #pragma unroll
        for (int ki=0; ki<K; ki++){
            int iy = oy*2 + ki - PAD;
            if (iy < 0 || iy >= HIN) continue;
            int rr = iy - iy0;
            #pragma unroll
            for (int kj=0; kj<K; kj++){
                int ix = ox*2 + kj - PAD;
                if (ix < 0 || ix >= HIN) continue;
                int sp = rr*HIN + ix;
                float w = as[sp];
                S0 += w;
                u64 wp = f2pk(w,w);
                const u64* wk2 = (const u64*)&ws[(ki*K+kj)*16];
                #pragma unroll
                for (int ii=0; ii<2; ii++){
                    int irow = half*2 + ii;
                    u64 pm2[4];
                    #pragma unroll
                    for (int j=0;j<4;j++){
                        float pj = ps[irow*4+j][sp];
                        pm2[j] = f2pk(pj,pj);
                    }
                    #pragma unroll
                    for (int l2=0;l2<2;l2++){
                        u64 vv = f2pk(0.f,0.f);
                        #pragma unroll
                        for (int j=0;j<4;j++)
                            vv = ffma2(pm2[j], wk2[j*2+l2], vv);
                        int a = ii*2 + l2;
                        T1p[a] = ffma2(wp, vv, T1p[a]);
                        T2p[a] = ffma2(fmul2(wp, vv), vv, T2p[a]);
                    }
                }
            }
        }
    }

    float hls_own = 0.0f;
    if (act){
        float inv = 1.0f/(S0 + EPSF);
        float mu[8];
        #pragma unroll
        for (int a=0;a<4;a++){
            float t1l,t1h,t2l,t2h;
            f2up(T1p[a],t1l,t1h); f2up(T2p[a],t2l,t2h);
            int ii = a>>1, l2 = a&1;
            int q0 = ii*4 + l2*2;
            float m0 = t1l*inv;
            float m1 = t1h*inv;
            mu[q0]   = m0;
            mu[q0+1] = m1;
            float sg0 = fmaxf((t2l - 2.0f*m0*t1l + m0*m0*S0)*inv, 0.0f) + EPSF;
            float sg1 = fmaxf((t2h - 2.0f*m1*t1h + m1*m1*S0)*inv, 0.0f) + EPSF;
            hls_own += 0.5f*logf(sg0) + 0.5f*logf(sg1);
        }
        size_t o = (size_t)((b*HOUT+oy)*HOUT+ox);
        float4* po = (float4*)&pose_out[o*(BC*16) + c*16 + half*8];
        float4 v4;
        v4.x=mu[0]; v4.y=mu[1]; v4.z=mu[2]; v4.w=mu[3]; po[0]=v4;
        v4.x=mu[4]; v4.y=mu[5]; v4.z=mu[6]; v4.w=mu[7]; po[1]=v4;
        if (half) s_h[pos_t] = hls_own;
    }
    __syncthreads();
    if (act && half == 0){
        float hls = hls_own + s_h[pos_t];
        float cost = (hls + 16.0f*bu[0]) * S0;
        float ao = sigmoidf_(LAMBDAF*(ba[0] - cost));
        size_t o = (size_t)((b*HOUT+oy)*HOUT+ox);
        a_out_g[o*BC + c] = ao;
    }
}

// ---------------- 1x1 conv caps: warp-per-position, smem-transpose softmax ----------------
template<int BIN, int WPB>
__global__ void __launch_bounds__(WPB*32) cc_warp_kernel(
    const float* __restrict__ pose_in,
    const float* __restrict__ a_g,
    const float* __restrict__ W,
    const float* __restrict__ bu, const float* __restrict__ ba,
    float* __restrict__ pose_out,
    float* __restrict__ a_out_g,
    int npos)
{
    __shared__ float sW[BIN*256];
    __shared__ float sv[WPB][BIN*8*32];
    __shared__ float s_ln[WPB][BIN*17];
    __shared__ float s_rw[WPB][BIN*17];
    __shared__ float s_ain[WPB][BIN];

    int tid = threadIdx.x;
    for (int i=tid; i<BIN*256; i+=WPB*32){
        int c2 = i & 15; int rest = i >> 4;
        int l = rest & 3; int j = (rest>>2)&3; int bin = rest>>4;
        sW[i] = W[(((size_t)bin*16 + c2)*4 + j)*4 + l];
    }
    __syncthreads();

    int warp = tid >> 5, lane = tid & 31;
    int pos = blockIdx.x*WPB + warp;
    if (pos >= npos) return;
    int c = lane & 15, half = lane >> 4;
    float* v   = sv[warp];
    float* lnp = s_ln[warp];
    float* rwp = s_rw[warp];
    float* ain = s_ain[warp];

    const float* pm = pose_in + (size_t)pos*BIN*16;
    const float* ag = a_g + (size_t)pos*BIN;
    if (half == 0 && c < BIN) ain[c] = ag[c];

    float T1[8], T2[8]; float S0 = 0.0f;
    #pragma unroll
    for (int q=0;q<8;q++){ T1[q]=0.0f; T2[q]=0.0f; }

    #pragma unroll
    for (int bin=0; bin<BIN; bin++){
        float w = ag[bin] * (1.0f/16.0f);
        S0 += w;
        const float4* pm4 = (const float4*)(pm + bin*16 + half*8);
        float4 p0 = pm4[0], p1 = pm4[1];
        float pmr[8] = {p0.x,p0.y,p0.z,p0.w,p1.x,p1.y,p1.z,p1.w};
        #pragma unroll
        for (int q=0;q<8;q++){
            int i0 = q>>2, l = q&3;
            float s = 0.0f;
            #pragma unroll
            for (int j=0;j<4;j++)
                s += pmr[i0*4+j] * sW[(((bin*4+j)*4+l)<<4) + c];
            v[(bin*8+q)*32 + lane] = s;
            T1[q] += w*s;
            T2[q] += w*s*s;
        }
    }

    float buC = bu[c], baC = ba[c];
    float mu[8], i2[8], cst = 0.0f, ao = 0.0f;
    {
        float inv = 1.0f/(S0 + EPSF);
        float hls = 0.0f;
        #pragma unroll
        for (int q=0;q<8;q++){
            float m = T1[q]*inv;
            mu[q] = m;
            float sg = fmaxf(T2[q]*inv - m*m, 0.0f) + EPSF;
            i2[q] = 0.5f/sg;
            hls += 0.5f*logf(sg);
        }
        hls += __shfl_xor_sync(0xffffffffu, hls, 16);
        float cost = (hls + 16.0f*buC) * S0;
        ao = sigmoidf_(LAMBDAF*(baC - cost));
        cst = -hls - 16.0f*LN2PI_HALF_F + logf(EPSF + ao);
    }

    #pragma unroll
    for (int it=0; it<2; it++){
        float part[BIN];
        #pragma unroll
        for (int bin=0;bin<BIN;bin++){
            float p0 = 0.0f;
            #pragma unroll
            for (int q=0;q<8;q++){
                float d = v[(bin*8+q)*32 + lane] - mu[q];
                p0 -= d*d*i2[q];
            }
            part[bin] = p0;
        }
        #pragma unroll
        for (int bin=0;bin<BIN;bin++)
            part[bin] += __shfl_xor_sync(0xffffffffu, part[bin], 16);
        if (half == 0){
            #pragma unroll
            for (int bin=0;bin<BIN;bin++)
                lnp[bin*17 + c] = part[bin] + cst;
        }
        __syncwarp();
        if (lane < BIN){
            float l16[16];
            float mx = -1e30f;
            #pragma unroll
            for (int c2=0;c2<16;c2++){ l16[c2] = lnp[lane*17 + c2]; mx = fmaxf(mx, l16[c2]); }
            float sum = 0.0f;
            #pragma unroll
            for (int c2=0;c2<16;c2++){ l16[c2] = expf(l16[c2]-mx); sum += l16[c2]; }
            float f = ain[lane]/sum;
            #pragma unroll
            for (int c2=0;c2<16;c2++) rwp[lane*17 + c2] = l16[c2]*f;
        }
        __syncwarp();
        float nT1[8], nT2[8]; float nS0 = 0.0f;
        #pragma unroll
        for (int q=0;q<8;q++){ nT1[q]=0.0f; nT2[q]=0.0f; }
        #pragma unroll
        for (int bin=0;bin<BIN;bin++){
            float w = rwp[bin*17 + c];
            nS0 += w;
            #pragma unroll
            for (int q=0;q<8;q++){
                float vq = v[(bin*8+q)*32 + lane];
                nT1[q] += w*vq;
                nT2[q] += w*vq*vq;
            }
        }
        float inv = 1.0f/(nS0 + EPSF);
        float hls = 0.0f;
        #pragma unroll
        for (int q=0;q<8;q++){
            float m = nT1[q]*inv;
            mu[q] = m;
            float sg = fmaxf(nT2[q]*inv - m*m, 0.0f) + EPSF;
            i2[q] = 0.5f/sg;
            hls += 0.5f*logf(sg);
        }
        hls += __shfl_xor_sync(0xffffffffu, hls, 16);
        float cost = (hls + 16.0f*buC) * nS0;
        ao = sigmoidf_(LAMBDAF*(baC - cost));
        if (it == 0) cst = -hls - 16.0f*LN2PI_HALF_F + logf(EPSF + ao);
    }

    size_t ob = (size_t)pos*256 + c*16 + half*8;
    #pragma unroll
    for (int q=0;q<8;q++) pose_out[ob+q] = mu[q];
    if (half == 0) a_out_g[(size_t)pos*16 + c] = ao;
}

// ---------------- class EM iter0: fused votes + reduce + finalize per (b,e) ----------------
__global__ void __launch_bounds__(256) cls_vred_kernel(
    const float* __restrict__ W,
    const float* __restrict__ bu, const float* __restrict__ ba)
{
    int be = blockIdx.x;
    int b = be / CLS_E, e = be % CLS_E;
    int tid = threadIdx.x, lane = tid & 31, warp = tid >> 5;

    __shared__ float sw[16*17];
    if (tid < 256){
        int d = tid >> 4, p = tid & 15;
        int j = p >> 2, l = p & 3;
        sw[d*17 + p] = W[((d*CLS_E + e)*4 + j)*4 + l];
    }
    __syncthreads();

    float s0 = 0.0f, s1[16], s2[16];
    #pragma unroll
    for (int q=0;q<16;q++){ s1[q]=0.0f; s2[q]=0.0f; }

    for (int bin=tid; bin<CLS_BIN; bin+=256){
        int d  = bin & 15;
        int ww = (bin >> 4) & 7;
        int hh = bin >> 7;
        const float4* pm4 = (const float4*)(g_pose5 + ((size_t)b*CLS_BIN + bin)*16);
        float4 P0 = pm4[0], P1 = pm4[1], P2 = pm4[2], P3 = pm4[3];
        float pmv[16] = {P0.x,P0.y,P0.z,P0.w, P1.x,P1.y,P1.z,P1.w,
                         P2.x,P2.y,P2.z,P2.w, P3.x,P3.y,P3.z,P3.w};
        float w = 0.1f * g_a5[(size_t)b*CLS_BIN + bin];
        s0 += w;
        float4* vout = (float4*)(g_votes + ((size_t)be*CLS_BIN + bin)*16);
        const float* swd = &sw[d*17];
        #pragma unroll
        for (int i=0;i<4;i++){
            float vv[4];
            #pragma unroll
            for (int l=0;l<4;l++){
                float s = 0.0f;
                #pragma unroll
                for (int j=0;j<4;j++) s += pmv[i*4+j]*swd[j*4+l];
                vv[l] = s;
            }
            if (i == 0){ vv[0] += (float)hh*0.125f; vv[1] += (float)ww*0.125f; }
            float4 o4; o4.x=vv[0]; o4.y=vv[1]; o4.z=vv[2]; o4.w=vv[3];
            vout[i] = o4;
            #pragma unroll
            for (int l=0;l<4;l++){
                s1[i*4+l] += w*vv[l];
                s2[i*4+l] += w*vv[l]*vv[l];
            }
        }
    }

    #pragma unroll
    for (int off=16; off; off>>=1){
        s0 += __shfl_xor_sync(0xffffffffu, s0, off);
        #pragma unroll
        for (int q=0;q<16;q++){
            s1[q] += __shfl_xor_sync(0xffffffffu, s1[q], off);
            s2[q] += __shfl_xor_sync(0xffffffffu, s2[q], off);
        }
    }
    __shared__ float red[8][33];
    __shared__ float smS[33];
    if (lane == 0){
        red[warp][0] = s0;
        #pragma unroll
        for (int q=0;q<16;q++){ red[warp][1+q]=s1[q]; red[warp][17+q]=s2[q]; }
    }
    __syncthreads();
    if (tid < 33){
        float t = 0.0f;
        #pragma unroll
        for (int w8=0;w8<8;w8++) t += red[w8][tid];
        smS[tid] = t;
    }
    __syncthreads();
    if (tid < 16){
        float S0 = smS[0];
        float S1 = smS[1+tid];
        float S2 = smS[17+tid];
        float inv = 1.0f/(S0 + EPSF);
        float m = S1*inv;
        float sg = fmaxf((S2 - 2.0f*m*S1 + m*m*S0)*inv, 0.0f) + EPSF;
        g_mu[(size_t)be*16 + tid] = m;
        g_i2[(size_t)be*16 + tid] = 0.5f/sg;
        float hl = 0.5f*logf(sg);
        #pragma unroll
        for (int off=8; off; off>>=1)
            hl += __shfl_xor_sync(0x0000ffffu, hl, off);
        if (tid == 0){
            float cost = (hl + 16.0f*bu[e]) * S0;
            float ao = sigmoidf_(LAMBDAF*(ba[e] - cost));
            g_cst[be] = -hl - 16.0f*LN2PI_HALF_F + logf(EPSF + ao);
        }
    }
}

// ---------------- class EM: reduce+finalize (reads stored votes + r) ----------------
__global__ void __launch_bounds__(256) cls_redfin_kernel(
    const float* __restrict__ bu, const float* __restrict__ ba,
    float* __restrict__ out, int last)
{
    int be = blockIdx.x;
    int b = be / CLS_E, e = be % CLS_E;
    const float* vb = g_votes + (size_t)be*CLS_BIN*16;
    const float* rr = g_r + (size_t)be*CLS_BIN;
    const float* ab = g_a5 + (size_t)b*CLS_BIN;
    int tid = threadIdx.x, lane = tid & 31, warp = tid >> 5;

    float s0 = 0.0f, s1[16], s2[16];
    #pragma unroll
    for (int q=0;q<16;q++){ s1[q]=0.0f; s2[q]=0.0f; }

    for (int bin=tid; bin<CLS_BIN; bin+=256){
        float w = rr[bin] * ab[bin];
        s0 += w;
        const float4* vv = (const float4*)(vb + (size_t)bin*16);
        #pragma unroll
        for (int q4=0;q4<4;q4++){
            float4 v4 = vv[q4];
            s1[q4*4+0] += w*v4.x; s2[q4*4+0] += w*v4.x*v4.x;
            s1[q4*4+1] += w*v4.y; s2[q4*4+1] += w*v4.y*v4.y;
            s1[q4*4+2] += w*v4.z; s2[q4*4+2] += w*v4.z*v4.z;
            s1[q4*4+3] += w*v4.w; s2[q4*4+3] += w*v4.w*v4.w;
        }
    }
    #pragma unroll
    for (int off=16; off; off>>=1){
        s0 += __shfl_xor_sync(0xffffffffu, s0, off);
        #pragma unroll
        for (int q=0;q<16;q++){
            s1[q] += __shfl_xor_sync(0xffffffffu, s1[q], off);
            s2[q] += __shfl_xor_sync(0xffffffffu, s2[q], off);
        }
    }
    __shared__ float red[8][33];
    __shared__ float smS[33];
    if (lane == 0){
        red[warp][0] = s0;
        #pragma unroll
        for (int q=0;q<16;q++){ red[warp][1+q]=s1[q]; red[warp][17+q]=s2[q]; }
    }
    __syncthreads();
    if (tid < 33){
        float t = 0.0f;
        #pragma unroll
        for (int w8=0;w8<8;w8++) t += red[w8][tid];
        smS[tid] = t;
    }
    __syncthreads();
    if (tid < 16){
        float S0 = smS[0];
        float S1 = smS[1+tid];
        float S2 = smS[17+tid];
        float inv = 1.0f/(S0 + EPSF);
        float m = S1*inv;
        float sg = fmaxf((S2 - 2.0f*m*S1 + m*m*S0)*inv, 0.0f) + EPSF;
        g_mu[(size_t)be*16 + tid] = m;
        g_i2[(size_t)be*16 + tid] = 0.5f/sg;
        float hl = 0.5f*logf(sg);
        #pragma unroll
        for (int off=8; off; off>>=1)
            hl += __shfl_xor_sync(0x0000ffffu, hl, off);
        if (tid == 0){
            float cost = (hl + 16.0f*bu[e]) * S0;
            float ao = sigmoidf_(LAMBDAF*(ba[e] - cost));
            g_cst[be] = -hl - 16.0f*LN2PI_HALF_F + logf(EPSF + ao);
            if (last) out[b*CLS_E + e] = ao;
        }
    }
}

// ---------------- class EM: E step ----------------
__global__ void __launch_bounds__(256) cls_estep_kernel()
{
    int idx = blockIdx.x*256 + threadIdx.x;
    if (idx >= NB*CLS_BIN) return;
    int b = idx >> 10, bin = idx & 1023;
    float lnap[CLS_E];
    float mx = -1e30f;
    #pragma unroll
    for (int e=0;e<CLS_E;e++){
        int be = b*CLS_E + e;
        const float4* vv = (const float4*)(g_votes + ((size_t)be*CLS_BIN + bin)*16);
        const float4* mm = (const float4*)(g_mu + (size_t)be*16);
        const float4* ii = (const float4*)(g_i2 + (size_t)be*16);
        float acc = 0.0f;
        #pragma unroll
        for (int q4=0;q4<4;q4++){
            float4 v4 = vv[q4], m4 = mm[q4], i4 = ii[q4];
            float d0=v4.x-m4.x, d1=v4.y-m4.y, d2=v4.z-m4.z, d3=v4.w-m4.w;
            acc -= d0*d0*i4.x + d1*d1*i4.y + d2*d2*i4.z + d3*d3*i4.w;
        }
        lnap[e] = acc + g_cst[be];
        mx = fmaxf(mx, lnap[e]);
    }
    float sum = 0.0f;
    #pragma unroll
    for (int e=0;e<CLS_E;e++){ lnap[e] = expf(lnap[e]-mx); sum += lnap[e]; }
    float isum = 1.0f/sum;
    #pragma unroll
    for (int e=0;e<CLS_E;e++)
        g_r[((size_t)(b*CLS_E+e))*CLS_BIN + bin] = lnap[e]*isum;
}

// ---------------- launch ----------------
extern "C" void kernel_launch(void* const* d_in, const int* in_sizes, int n_in,
                              void* d_out, int out_size)
{
    const float* x       = (const float*)d_in[0];
    const float* conv1_w = (const float*)d_in[1];
    const float* conv1_b = (const float*)d_in[2];
    const float* ppw     = (const float*)d_in[3];
    const float* ppb     = (const float*)d_in[4];
    const float* paw     = (const float*)d_in[5];
    const float* pab     = (const float*)d_in[6];
    const float* dw1_w   = (const float*)d_in[7];
    const float* dw1_bu  = (const float*)d_in[8];
    const float* dw1_ba  = (const float*)d_in[9];
    const float* cc1_w   = (const float*)d_in[10];
    const float* cc1_bu  = (const float*)d_in[11];
    const float* cc1_ba  = (const float*)d_in[12];
    const float* dw2_w   = (const float*)d_in[13];
    const float* dw2_bu  = (const float*)d_in[14];
    const float* dw2_ba  = (const float*)d_in[15];
    const float* cc2_w   = (const float*)d_in[16];
    const float* cc2_bu  = (const float*)d_in[17];
    const float* cc2_ba  = (const float*)d_in[18];
    const float* cls_w   = (const float*)d_in[19];
    const float* cls_bu  = (const float*)d_in[20];
    const float* cls_ba  = (const float*)d_in[21];
    float* out = (float*)d_out;

    float *p1,*a1,*p2,*a2,*p3,*a3,*p4,*a4,*p5,*a5;
    cudaGetSymbolAddress((void**)&p1, g_pose1);
    cudaGetSymbolAddress((void**)&a1, g_a1);
    cudaGetSymbolAddress((void**)&p2, g_pose2);
    cudaGetSymbolAddress((void**)&a2, g_a2);
    cudaGetSymbolAddress((void**)&p3, g_pose3);
    cudaGetSymbolAddress((void**)&a3, g_a3);
    cudaGetSymbolAddress((void**)&p4, g_pose4);
    cudaGetSymbolAddress((void**)&a4, g_a4);
    cudaGetSymbolAddress((void**)&p5, g_pose5);
    cudaGetSymbolAddress((void**)&a5, g_a5);

    {   const int smem_bytes = CP_SMEM_FLOATS * 4;
        cudaFuncSetAttribute(convprim_kernel,
                             cudaFuncAttributeMaxDynamicSharedMemorySize, smem_bytes);
        convprim_kernel<<<NB*15, 256, smem_bytes>>>(
            x, conv1_w, conv1_b, ppw, ppb, paw, pab);
    }
    {   int grid = NB*B1*2;
        dw_tile_kernel<7,3,H1,H2,B1,8,256><<<grid, 256>>>(
            p1, a1, dw1_w, dw1_bu, dw1_ba, p2, a2); }
    {   int npos = NB*H2*H2;                 // 7200
        cc_warp_kernel<CC1_IN, 4><<<(npos+3)/4, 128>>>(
            p2, a2, cc1_w, cc1_bu, cc1_ba, p3, a3, npos); }
    {   int grid = NB*CC1_OUT*1;
        dw_tile_kernel<5,2,H2,H3,CC1_OUT,8,128><<<grid, 128>>>(
            p3, a3, dw2_w, dw2_bu, dw2_ba, p4, a4); }
    {   int npos = NB*H3*H3;                 // 2048
        cc_warp_kernel<CC2_IN, 4><<<(npos+3)/4, 128>>>(
            p4, a4, cc2_w, cc2_bu, cc2_ba, p5, a5, npos); }
    {
        int nbe = NB*CLS_E;                  // 320
        int nbins = NB*CLS_BIN;              // 32768
        cls_vred_kernel<<<nbe, 256>>>(cls_w, cls_bu, cls_ba);
        cls_estep_kernel<<<(nbins+255)/256, 256>>>();
        cls_redfin_kernel<<<nbe, 256>>>(cls_bu, cls_ba, out, 0);
        cls_estep_kernel<<<(nbins+255)/256, 256>>>();
        cls_redfin_kernel<<<nbe, 256>>>(cls_bu, cls_ba, out, 1);
    }
}